// round 3
// baseline (speedup 1.0000x reference)
#include <cuda_runtime.h>
#include <cuda_bf16.h>
#include <cstdint>
#include <cstddef>

// ---------------------------------------------------------------------------
// Problem constants
//   B=2, DIM=256, H=W=64, HEADS=8 (HC=32), HG=2 (GC=128), STRIDE=2,
//   WS=8 (NW=64 windows of WT=64 queries), RH=RW=32 (R=1024), MLP_HID=1024
// ---------------------------------------------------------------------------

#define NB      2
#define CDIM    256
#define HWPIX   4096            // 64*64
#define HEADS   8
#define HC      32
#define HG      2
#define GC      128
#define RPTS    1024            // R
#define NWIN    64              // NW
#define NPIX_S  65536           // NW * R
#define MLPH    1024

// ----------------------------- scratch ------------------------------------
__device__ float g_xaT [NB * HWPIX * CDIM];            // LN1 out, pixel-major
__device__ float g_q   [NB * CDIM * HWPIX];            // q conv out, C-major
__device__ float g_t1  [4 * 128 * 32 * 32];
__device__ float g_t2  [4 * 128 * 16 * 16];
__device__ float g_t3  [4 * 128 * 8 * 8];
__device__ float g_oT  [4 * 64 * 128];                 // bn+gelu out, pixel-major
__device__ float g_offr[4 * 2048 * 64];                // off4 out, C-major
__device__ float g_sampT[(size_t)NB * NPIX_S * CDIM];  // sampled, pixel-major
__device__ float g_kk  [(size_t)NB * CDIM * NPIX_S];   // C-major
__device__ float g_vv  [(size_t)NB * CDIM * NPIX_S];   // C-major
__device__ float g_attnT[NB * HWPIX * CDIM];           // attention out, pixel-major
__device__ float g_x2  [NB * HWPIX * CDIM];            // x + proj, pixel-major
__device__ float g_xmT [NB * HWPIX * CDIM];            // LN2 out, pixel-major
__device__ float g_hidT[(size_t)NB * HWPIX * MLPH];    // mlp hidden, pixel-major

// ----------------------------- helpers ------------------------------------
__device__ __forceinline__ float geluf(float v) {
    return 0.5f * v * (1.0f + erff(v * 0.70710678118654752f));
}

// Fast exp on the FMA pipe (avoids MUFU EX2: rt_SMSP=8 -> ~140G/s chip ceiling
// vs 67M softmax exps). Degree-5 poly for 2^f, rel err ~8e-5.
__device__ __forceinline__ float fexp(float x) {
    float y = x * 1.4426950408889634f;
    y = fmaxf(y, -126.0f);
    float fi = floorf(y);
    float f = y - fi;
    float p = 0.0013333558f;
    p = fmaf(p, f, 0.0096181291f);
    p = fmaf(p, f, 0.0555041087f);
    p = fmaf(p, f, 0.2402264923f);
    p = fmaf(p, f, 0.6931471806f);
    p = fmaf(p, f, 1.0f);
    int e = (int)fi;
    return p * __int_as_float((e + 127) << 23);
}

// ----------------------------- LayerNorm -----------------------------------
// One block per pixel (256 threads = channels). Reads with arbitrary strides,
// writes pixel-major outT[p*256 + c].
__global__ __launch_bounds__(256) void ln_kernel(
    const float* __restrict__ in, const float* __restrict__ gam,
    const float* __restrict__ bet, float* __restrict__ outT,
    size_t bStride, size_t cStride, size_t pStride)
{
    int p  = blockIdx.x;            // 0..8191
    int b  = p >> 12;
    int hw = p & 4095;
    const float* ip = in + (size_t)b * bStride + (size_t)hw * pStride;
    int c = threadIdx.x;
    float v = ip[(size_t)c * cStride];
    float s1 = v, s2 = v * v;
    #pragma unroll
    for (int d = 16; d > 0; d >>= 1) {
        s1 += __shfl_xor_sync(0xffffffffu, s1, d);
        s2 += __shfl_xor_sync(0xffffffffu, s2, d);
    }
    __shared__ float sm1[8], sm2[8];
    __shared__ float mu_s, ri_s;
    int wid = c >> 5;
    if ((c & 31) == 0) { sm1[wid] = s1; sm2[wid] = s2; }
    __syncthreads();
    if (c == 0) {
        float t1 = 0.f, t2 = 0.f;
        #pragma unroll
        for (int i = 0; i < 8; i++) { t1 += sm1[i]; t2 += sm2[i]; }
        float mu  = t1 * (1.0f / 256.0f);
        float var = t2 * (1.0f / 256.0f) - mu * mu;
        mu_s = mu;
        ri_s = rsqrtf(var + 1e-5f);
    }
    __syncthreads();
    outT[(size_t)p * 256 + c] = (v - mu_s) * ri_s * gam[c] + bet[c];
}

// ----------------------------- GEMM (TN) ------------------------------------
// C[b] = A(MxK) * B[b](NxK)^T (+bias) (gelu?) (+res?), out C-major or N-major.
// Tiles: BM=128, BN=64, BK=16, 256 threads, 8x4 per-thread microtile.
// All problem sizes divide the tiles exactly (no bounds checks).
#define GF_OUT_NMAJOR 1
#define GF_RES_NMAJOR 2
#define GF_GELU       4

__global__ __launch_bounds__(256) void gemm_tn(
    const float* __restrict__ A, const float* __restrict__ Bm,
    const float* __restrict__ bias, const float* __restrict__ res,
    float* __restrict__ C, int M, int N, int K, int flags)
{
    __shared__ float As[16][132];
    __shared__ float Bs[16][68];
    const int b  = blockIdx.z;
    const int m0 = blockIdx.y * 128;
    const int n0 = blockIdx.x * 64;
    const float* Bb = Bm + (size_t)b * (size_t)N * (size_t)K;
    const int tid = threadIdx.x;
    const int lr = tid >> 2;          // 0..63
    const int lc = (tid & 3) << 2;    // 0,4,8,12
    const int ty = tid >> 4;          // 0..15
    const int tx = tid & 15;          // 0..15

    float acc[8][4];
    #pragma unroll
    for (int i = 0; i < 8; i++)
        #pragma unroll
        for (int j = 0; j < 4; j++) acc[i][j] = 0.f;

    for (int k0 = 0; k0 < K; k0 += 16) {
        float4 a0 = *(const float4*)(A  + (size_t)(m0 + lr)      * K + k0 + lc);
        float4 a1 = *(const float4*)(A  + (size_t)(m0 + lr + 64) * K + k0 + lc);
        float4 b0 = *(const float4*)(Bb + (size_t)(n0 + lr)      * K + k0 + lc);
        As[lc    ][lr]      = a0.x; As[lc + 1][lr]      = a0.y;
        As[lc + 2][lr]      = a0.z; As[lc + 3][lr]      = a0.w;
        As[lc    ][lr + 64] = a1.x; As[lc + 1][lr + 64] = a1.y;
        As[lc + 2][lr + 64] = a1.z; As[lc + 3][lr + 64] = a1.w;
        Bs[lc    ][lr] = b0.x; Bs[lc + 1][lr] = b0.y;
        Bs[lc + 2][lr] = b0.z; Bs[lc + 3][lr] = b0.w;
        __syncthreads();
        #pragma unroll
        for (int kk = 0; kk < 16; kk++) {
            float ar[8], br[4];
            #pragma unroll
            for (int i = 0; i < 8; i++) ar[i] = As[kk][ty * 8 + i];
            #pragma unroll
            for (int j = 0; j < 4; j++) br[j] = Bs[kk][tx * 4 + j];
            #pragma unroll
            for (int i = 0; i < 8; i++)
                #pragma unroll
                for (int j = 0; j < 4; j++)
                    acc[i][j] = fmaf(ar[i], br[j], acc[i][j]);
        }
        __syncthreads();
    }

    #pragma unroll
    for (int i = 0; i < 8; i++) {
        int m = m0 + ty * 8 + i;
        float bv = bias ? bias[m] : 0.f;
        #pragma unroll
        for (int j = 0; j < 4; j++) {
            int n = n0 + tx * 4 + j;
            float v = acc[i][j] + bv;
            if (flags & GF_GELU) v = geluf(v);
            if (res) {
                size_t ri = (flags & GF_RES_NMAJOR)
                    ? ((size_t)b * N + n) * (size_t)M + m
                    : ((size_t)b * M + m) * (size_t)N + n;
                v += res[ri];
            }
            size_t oi = (flags & GF_OUT_NMAJOR)
                ? ((size_t)b * N + n) * (size_t)M + m
                : ((size_t)b * M + m) * (size_t)N + n;
            C[oi] = v;
        }
    }
}

// ------------------------ depthwise 3x3 stride-2 ---------------------------
__global__ void dw_conv(const float* __restrict__ in, const float* __restrict__ w,
                        float* __restrict__ out, int Hi, int Ho)
{
    int idx = blockIdx.x * blockDim.x + threadIdx.x;
    int total = 4 * 128 * Ho * Ho;
    if (idx >= total) return;
    int ox = idx % Ho;
    int oy = (idx / Ho) % Ho;
    int c  = (idx / (Ho * Ho)) % 128;
    int g  = idx / (Ho * Ho * 128);
    const float* ip = in + (size_t)(g * 128 + c) * Hi * Hi;
    const float* wp = w + c * 9;
    float s = 0.f;
    #pragma unroll
    for (int ky = 0; ky < 3; ky++) {
        int iy = oy * 2 - 1 + ky;
        if (iy < 0 || iy >= Hi) continue;
        #pragma unroll
        for (int kx = 0; kx < 3; kx++) {
            int ix = ox * 2 - 1 + kx;
            if (ix < 0 || ix >= Hi) continue;
            s = fmaf(ip[iy * Hi + ix], wp[ky * 3 + kx], s);
        }
    }
    out[idx] = s;
}

// ------------------------- BN + GELU + transpose ---------------------------
// t3 (4,128,64) C-major -> oT (4,64,128) pixel-major
__global__ void bn_gelu_t(const float* __restrict__ t3, const float* __restrict__ g,
                          const float* __restrict__ b, const float* __restrict__ m,
                          const float* __restrict__ v, float* __restrict__ oT)
{
    int idx = blockIdx.x * blockDim.x + threadIdx.x;
    if (idx >= 4 * 128 * 64) return;
    int wsp = idx % 64;
    int c   = (idx / 64) % 128;
    int gg  = idx / (64 * 128);
    float x = t3[idx];
    x = (x - m[c]) * rsqrtf(v[c] + 1e-5f) * g[c] + b[c];
    x = geluf(x);
    oT[(size_t)(gg * 64 + wsp) * 128 + c] = x;
}

// ------------------------------ grid sample --------------------------------
// One block per sample point (g,w,r), 128 threads = channels of the group.
// Reads xaT pixel-major (coalesced 512B per corner), writes sampT pixel-major.
__global__ __launch_bounds__(128) void grid_sample_k(
    const float* __restrict__ offr, const float* __restrict__ xaT,
    float* __restrict__ sampT)
{
    int blk = blockIdx.x;           // 4*64*1024
    int g = blk >> 16;
    int w = (blk >> 10) & 63;
    int r = blk & 1023;
    int b  = g >> 1;
    int hg = g & 1;
    int ri = r >> 5;
    int ci = r & 31;

    float offRow = offr[(size_t)(g * 2048 + r) * 64 + w];
    float offCol = offr[(size_t)(g * 2048 + 1024 + r) * 64 + w];
    // rows = ((tanh(off)*2/64 + ref)+1)*0.5*63 ; ref = 4*ri/63 - 1
    float rows = fmaf(tanhf(offRow), 0.984375f, (float)(ri * 2));
    float cols = fmaf(tanhf(offCol), 0.984375f, (float)(ci * 2));
    float r0f = floorf(rows), c0f = floorf(cols);
    float wr = rows - r0f, wc = cols - c0f;
    int r0 = (int)r0f, c0 = (int)c0f;

    int ch = threadIdx.x;
    const float* src = xaT + ((size_t)b * HWPIX) * 256 + hg * 128 + ch;

    float v00 = 0.f, v01 = 0.f, v10 = 0.f, v11 = 0.f;
    if (r0 >= 0 && r0 < 64) {
        if (c0 >= 0 && c0 < 64)         v00 = src[(size_t)(r0 * 64 + c0) * 256];
        if (c0 + 1 >= 0 && c0 + 1 < 64) v01 = src[(size_t)(r0 * 64 + c0 + 1) * 256];
    }
    if (r0 + 1 >= 0 && r0 + 1 < 64) {
        if (c0 >= 0 && c0 < 64)         v10 = src[(size_t)((r0 + 1) * 64 + c0) * 256];
        if (c0 + 1 >= 0 && c0 + 1 < 64) v11 = src[(size_t)((r0 + 1) * 64 + c0 + 1) * 256];
    }
    float v = v00 * (1.f - wr) * (1.f - wc) + v01 * (1.f - wr) * wc
            + v10 * wr * (1.f - wc)         + v11 * wr * wc;
    sampT[((size_t)b * NPIX_S + (size_t)w * 1024 + r) * 256 + hg * 128 + ch] = v;
}

// ------------------------------ attention ----------------------------------
// One block per (b, head, window). 256 threads = 64 queries x 4 r-lanes.
// wq in registers (32), kk/vv tiles staged in smem, online softmax with
// FFMA-pipe exp, relative-position bias gathered from L2-resident posembed.
__global__ __launch_bounds__(256, 2) void attn_kernel(
    const float* __restrict__ qb, const float* __restrict__ kk,
    const float* __restrict__ vv, const float* __restrict__ pos,
    float* __restrict__ outT)
{
    __shared__ float wq_s[64][33];
    __shared__ float kk_s[32][68];
    __shared__ float vv_s[32][68];
    const int w = blockIdx.x, h = blockIdx.y, b = blockIdx.z;
    const int wh = w >> 3, wwx = w & 7;
    const int tid = threadIdx.x;

    for (int e = tid; e < 2048; e += 256) {
        int qq = e >> 5, c = e & 31;
        int yy = (wh << 3) + (qq >> 3), xx = (wwx << 3) + (qq & 7);
        wq_s[qq][c] = qb[(size_t)(b * 256 + h * 32 + c) * HWPIX + yy * 64 + xx] * 0.0625f;
    }
    __syncthreads();

    const int q = tid >> 2, lane = tid & 3;
    const int y = (wh << 3) + (q >> 3), x = (wwx << 3) + (q & 7);
    float wqr[32];
    #pragma unroll
    for (int c = 0; c < 32; c++) wqr[c] = wq_s[q][c];

    const float* posh = pos + h * 127 * 127 + (63 - y) * 127 + (63 - x);
    float m = -1e30f, s = 0.f;
    float acc[32];
    #pragma unroll
    for (int c = 0; c < 32; c++) acc[c] = 0.f;

    const size_t base = (size_t)(b * 256 + h * 32) * NPIX_S + (size_t)w * 1024;
    const int lch = tid >> 3, lrr = (tid & 7) << 3;

    for (int r0 = 0; r0 < 1024; r0 += 64) {
        __syncthreads();
        {
            const float* kp = kk + base + (size_t)lch * NPIX_S + r0 + lrr;
            const float* vp = vv + base + (size_t)lch * NPIX_S + r0 + lrr;
            float4 k0 = *(const float4*)kp;  float4 k1 = *(const float4*)(kp + 4);
            float4 v0 = *(const float4*)vp;  float4 v1 = *(const float4*)(vp + 4);
            *(float4*)&kk_s[lch][lrr]     = k0;
            *(float4*)&kk_s[lch][lrr + 4] = k1;
            *(float4*)&vv_s[lch][lrr]     = v0;
            *(float4*)&vv_s[lch][lrr + 4] = v1;
        }
        __syncthreads();

        for (int t = 0; t < 16; t++) {
            int rr = (t << 2) + lane;
            int r  = r0 + rr;
            float sc = posh[((r >> 5) << 1) * 127 + ((r & 31) << 1)];
            #pragma unroll
            for (int c = 0; c < 32; c++) sc = fmaf(wqr[c], kk_s[c][rr], sc);
            if (sc > m) {
                float corr = fexp(m - sc);
                s = fmaf(s, corr, 1.0f);
                #pragma unroll
                for (int c = 0; c < 32; c++) acc[c] = fmaf(acc[c], corr, vv_s[c][rr]);
                m = sc;
            } else {
                float p = fexp(sc - m);
                s += p;
                #pragma unroll
                for (int c = 0; c < 32; c++) acc[c] = fmaf(p, vv_s[c][rr], acc[c]);
            }
        }
    }

    // merge 4 lanes of each query (adjacent threads within a warp)
    float M = m;
    M = fmaxf(M, __shfl_xor_sync(0xffffffffu, M, 1));
    M = fmaxf(M, __shfl_xor_sync(0xffffffffu, M, 2));
    float corr = fexp(m - M);
    s *= corr;
    s += __shfl_xor_sync(0xffffffffu, s, 1);
    s += __shfl_xor_sync(0xffffffffu, s, 2);
    #pragma unroll
    for (int c = 0; c < 32; c++) {
        float a = acc[c] * corr;
        a += __shfl_xor_sync(0xffffffffu, a, 1);
        a += __shfl_xor_sync(0xffffffffu, a, 2);
        acc[c] = a;
    }
    if (lane == 0) {
        float inv = 1.0f / s;
        float* op = outT + ((size_t)b * HWPIX + y * 64 + x) * 256 + h * 32;
        #pragma unroll
        for (int c = 0; c < 32; c++) op[c] = acc[c] * inv;
    }
}

// ------------------------------ launch -------------------------------------
extern "C" void kernel_launch(void* const* d_in, const int* in_sizes, int n_in,
                              void* d_out, int out_size)
{
    const float* x      = (const float*)d_in[0];
    const float* ln1_g  = (const float*)d_in[1];
    const float* ln1_b  = (const float*)d_in[2];
    const float* q_w    = (const float*)d_in[3];
    const float* q_b    = (const float*)d_in[4];
    const float* k_w    = (const float*)d_in[5];
    const float* k_b    = (const float*)d_in[6];
    const float* v_w    = (const float*)d_in[7];
    const float* v_b    = (const float*)d_in[8];
    const float* off1_w = (const float*)d_in[9];
    const float* off2_w = (const float*)d_in[10];
    const float* off3_w = (const float*)d_in[11];
    const float* bn_g   = (const float*)d_in[12];
    const float* bn_b   = (const float*)d_in[13];
    const float* bn_m   = (const float*)d_in[14];
    const float* bn_v   = (const float*)d_in[15];
    const float* off4_w = (const float*)d_in[16];
    const float* pos    = (const float*)d_in[17];
    const float* proj_w = (const float*)d_in[18];
    const float* proj_b = (const float*)d_in[19];
    const float* ln2_g  = (const float*)d_in[20];
    const float* ln2_b  = (const float*)d_in[21];
    const float* mlp_w1 = (const float*)d_in[22];
    const float* mlp_b1 = (const float*)d_in[23];
    const float* mlp_w2 = (const float*)d_in[24];
    const float* mlp_b2 = (const float*)d_in[25];
    float* out = (float*)d_out;

    float *xaT, *q, *t1, *t2, *t3, *oT, *offr, *sampT, *kkb, *vvb, *attnT, *x2, *xmT, *hidT;
    cudaGetSymbolAddress((void**)&xaT,   g_xaT);
    cudaGetSymbolAddress((void**)&q,     g_q);
    cudaGetSymbolAddress((void**)&t1,    g_t1);
    cudaGetSymbolAddress((void**)&t2,    g_t2);
    cudaGetSymbolAddress((void**)&t3,    g_t3);
    cudaGetSymbolAddress((void**)&oT,    g_oT);
    cudaGetSymbolAddress((void**)&offr,  g_offr);
    cudaGetSymbolAddress((void**)&sampT, g_sampT);
    cudaGetSymbolAddress((void**)&kkb,   g_kk);
    cudaGetSymbolAddress((void**)&vvb,   g_vv);
    cudaGetSymbolAddress((void**)&attnT, g_attnT);
    cudaGetSymbolAddress((void**)&x2,    g_x2);
    cudaGetSymbolAddress((void**)&xmT,   g_xmT);
    cudaGetSymbolAddress((void**)&hidT,  g_hidT);

    // 1. LN1: x (B,C,HW) C-major -> xaT pixel-major
    ln_kernel<<<8192, 256>>>(x, ln1_g, ln1_b, xaT,
                             (size_t)CDIM * HWPIX, (size_t)HWPIX, (size_t)1);

    // 2. q = q_w @ xa + q_b  -> C-major (B,256,4096)
    gemm_tn<<<dim3(HWPIX / 64, CDIM / 128, NB), 256>>>(
        q_w, xaT, q_b, nullptr, q, CDIM, HWPIX, CDIM, 0);

    // 3. offset path: 3x depthwise stride-2 convs (q viewed as (4,128,64,64))
    dw_conv<<<(4 * 128 * 32 * 32 + 255) / 256, 256>>>(q,  off1_w, t1, 64, 32);
    dw_conv<<<(4 * 128 * 16 * 16 + 255) / 256, 256>>>(t1, off2_w, t2, 32, 16);
    dw_conv<<<(4 * 128 *  8 *  8 + 255) / 256, 256>>>(t2, off3_w, t3, 16, 8);

    // 4. BN + GELU, transpose to pixel-major
    bn_gelu_t<<<(4 * 128 * 64 + 255) / 256, 256>>>(t3, bn_g, bn_b, bn_m, bn_v, oT);

    // 5. off4: (2048x128) @ (64x128)^T per group -> offr C-major (4,2048,64)
    gemm_tn<<<dim3(1, 2048 / 128, 4), 256>>>(
        off4_w, oT, nullptr, nullptr, offr, 2048, 64, 128, 0);

    // 6. deformable bilinear sampling -> sampT pixel-major (B,65536,256)
    grid_sample_k<<<4 * 64 * 1024, 128>>>(offr, xaT, sampT);

    // 7/8. k,v 1x1 convs on sampled tensor -> C-major (B,256,65536)
    gemm_tn<<<dim3(NPIX_S / 64, CDIM / 128, NB), 256>>>(
        k_w, sampT, k_b, nullptr, kkb, CDIM, NPIX_S, CDIM, 0);
    gemm_tn<<<dim3(NPIX_S / 64, CDIM / 128, NB), 256>>>(
        v_w, sampT, v_b, nullptr, vvb, CDIM, NPIX_S, CDIM, 0);

    // 9. windowed attention with rel-pos bias -> attnT pixel-major
    attn_kernel<<<dim3(NWIN, HEADS, NB), 256>>>(q, kkb, vvb, pos, attnT);

    // 10. proj + residual(x, C-major) -> x2 pixel-major
    gemm_tn<<<dim3(HWPIX / 64, CDIM / 128, NB), 256>>>(
        proj_w, attnT, proj_b, x, x2, CDIM, HWPIX, CDIM, GF_OUT_NMAJOR);

    // 11. LN2 on x2 (pixel-major) -> xmT pixel-major
    ln_kernel<<<8192, 256>>>(x2, ln2_g, ln2_b, xmT,
                             (size_t)HWPIX * CDIM, (size_t)1, (size_t)CDIM);

    // 12. mlp1 + gelu -> hidT pixel-major (B,4096,1024)
    gemm_tn<<<dim3(HWPIX / 64, MLPH / 128, NB), 256>>>(
        mlp_w1, xmT, mlp_b1, nullptr, hidT, MLPH, HWPIX, CDIM,
        GF_OUT_NMAJOR | GF_GELU);

    // 13. mlp2 + residual(x2, pixel-major) -> out C-major (B,256,64,64)
    gemm_tn<<<dim3(HWPIX / 64, CDIM / 128, NB), 256>>>(
        mlp_w2, hidT, mlp_b2, x2, out, CDIM, HWPIX, MLPH, GF_RES_NMAJOR);
}

// round 4
// speedup vs baseline: 1.3535x; 1.3535x over previous
#include <cuda_runtime.h>
#include <cuda_bf16.h>
#include <cstdint>
#include <cstddef>

// ---------------------------------------------------------------------------
// Problem constants
//   B=2, DIM=256, H=W=64, HEADS=8 (HC=32), HG=2 (GC=128), STRIDE=2,
//   WS=8 (NW=64 windows of WT=64 queries), RH=RW=32 (R=1024), MLP_HID=1024
// ---------------------------------------------------------------------------

#define NB      2
#define CDIM    256
#define HWPIX   4096            // 64*64
#define HEADS   8
#define HC      32
#define HG      2
#define GC      128
#define RPTS    1024            // R
#define NWIN    64              // NW
#define NPIX_S  65536           // NW * R
#define MLPH    1024

// ----------------------------- scratch ------------------------------------
__device__ float g_xaT [NB * HWPIX * CDIM];            // LN1 out, pixel-major
__device__ float g_q   [NB * CDIM * HWPIX];            // q conv out, C-major
__device__ float g_t1  [4 * 128 * 32 * 32];
__device__ float g_t2  [4 * 128 * 16 * 16];
__device__ float g_t3  [4 * 128 * 8 * 8];
__device__ float g_oT  [4 * 64 * 128];                 // bn+gelu out, pixel-major
__device__ float g_offr[4 * 2048 * 64];                // off4 out, C-major
__device__ float g_pk  [4 * HWPIX * CDIM];             // partial k maps, pixel-major
__device__ float g_pv  [4 * HWPIX * CDIM];             // partial v maps, pixel-major
__device__ float g_kk  [(size_t)NB * NPIX_S * CDIM];   // kk pixel-major [(b,w,r),c]
__device__ float g_vv  [(size_t)NB * NPIX_S * CDIM];   // vv pixel-major
__device__ float g_attnT[NB * HWPIX * CDIM];           // attention out, pixel-major
__device__ float g_x2  [NB * HWPIX * CDIM];            // x + proj, pixel-major
__device__ float g_xmT [NB * HWPIX * CDIM];            // LN2 out, pixel-major
__device__ float g_hidT[(size_t)NB * HWPIX * MLPH];    // mlp hidden, pixel-major

// ----------------------------- helpers ------------------------------------
__device__ __forceinline__ float geluf(float v) {
    return 0.5f * v * (1.0f + erff(v * 0.70710678118654752f));
}

// Fast exp on the FMA pipe (avoids MUFU EX2: rt_SMSP=8 -> ~140G/s chip ceiling
// vs 67M softmax exps). Degree-5 poly for 2^f, rel err ~8e-5.
__device__ __forceinline__ float fexp(float x) {
    float y = x * 1.4426950408889634f;
    y = fmaxf(y, -126.0f);
    float fi = floorf(y);
    float f = y - fi;
    float p = 0.0013333558f;
    p = fmaf(p, f, 0.0096181291f);
    p = fmaf(p, f, 0.0555041087f);
    p = fmaf(p, f, 0.2402264923f);
    p = fmaf(p, f, 0.6931471806f);
    p = fmaf(p, f, 1.0f);
    int e = (int)fi;
    return p * __int_as_float((e + 127) << 23);
}

// ----------------------------- LayerNorm -----------------------------------
__global__ __launch_bounds__(256) void ln_kernel(
    const float* __restrict__ in, const float* __restrict__ gam,
    const float* __restrict__ bet, float* __restrict__ outT,
    size_t bStride, size_t cStride, size_t pStride)
{
    int p  = blockIdx.x;            // 0..8191
    int b  = p >> 12;
    int hw = p & 4095;
    const float* ip = in + (size_t)b * bStride + (size_t)hw * pStride;
    int c = threadIdx.x;
    float v = ip[(size_t)c * cStride];
    float s1 = v, s2 = v * v;
    #pragma unroll
    for (int d = 16; d > 0; d >>= 1) {
        s1 += __shfl_xor_sync(0xffffffffu, s1, d);
        s2 += __shfl_xor_sync(0xffffffffu, s2, d);
    }
    __shared__ float sm1[8], sm2[8];
    __shared__ float mu_s, ri_s;
    int wid = c >> 5;
    if ((c & 31) == 0) { sm1[wid] = s1; sm2[wid] = s2; }
    __syncthreads();
    if (c == 0) {
        float t1 = 0.f, t2 = 0.f;
        #pragma unroll
        for (int i = 0; i < 8; i++) { t1 += sm1[i]; t2 += sm2[i]; }
        float mu  = t1 * (1.0f / 256.0f);
        float var = t2 * (1.0f / 256.0f) - mu * mu;
        mu_s = mu;
        ri_s = rsqrtf(var + 1e-5f);
    }
    __syncthreads();
    outT[(size_t)p * 256 + c] = (v - mu_s) * ri_s * gam[c] + bet[c];
}

// ----------------------------- GEMM (TN) ------------------------------------
// C[z] = A(MxK, lda) * B[z](NxK, ldb)^T (+bias)(gelu?)(+res?), flexible strides.
// GF_GROUPED: z = b*2+g -> A += g*128, B = Bm + b*HWPIX*256 + g*128 (partial convs)
#define GF_OUT_NMAJOR 1
#define GF_RES_NMAJOR 2
#define GF_GELU       4
#define GF_GROUPED    8

__global__ __launch_bounds__(256) void gemm_tn(
    const float* __restrict__ A, int lda,
    const float* __restrict__ Bm, int ldb, size_t bZ,
    const float* __restrict__ bias, const float* __restrict__ res,
    float* __restrict__ C, int M, int N, int K, int flags)
{
    __shared__ float As[16][132];
    __shared__ float Bs[16][68];
    const int b  = blockIdx.z;
    const int m0 = blockIdx.y * 128;
    const int n0 = blockIdx.x * 64;
    const float* Ab = A;
    const float* Bb;
    if (flags & GF_GROUPED) {
        Ab = A + (b & 1) * 128;
        Bb = Bm + (size_t)(b >> 1) * ((size_t)HWPIX * 256) + (b & 1) * 128;
    } else {
        Bb = Bm + (size_t)b * bZ;
    }
    const int tid = threadIdx.x;
    const int lr = tid >> 2;          // 0..63
    const int lc = (tid & 3) << 2;    // 0,4,8,12
    const int ty = tid >> 4;          // 0..15
    const int tx = tid & 15;          // 0..15

    float acc[8][4];
    #pragma unroll
    for (int i = 0; i < 8; i++)
        #pragma unroll
        for (int j = 0; j < 4; j++) acc[i][j] = 0.f;

    for (int k0 = 0; k0 < K; k0 += 16) {
        float4 a0 = *(const float4*)(Ab + (size_t)(m0 + lr)      * lda + k0 + lc);
        float4 a1 = *(const float4*)(Ab + (size_t)(m0 + lr + 64) * lda + k0 + lc);
        float4 b0 = *(const float4*)(Bb + (size_t)(n0 + lr)      * ldb + k0 + lc);
        As[lc    ][lr]      = a0.x; As[lc + 1][lr]      = a0.y;
        As[lc + 2][lr]      = a0.z; As[lc + 3][lr]      = a0.w;
        As[lc    ][lr + 64] = a1.x; As[lc + 1][lr + 64] = a1.y;
        As[lc + 2][lr + 64] = a1.z; As[lc + 3][lr + 64] = a1.w;
        Bs[lc    ][lr] = b0.x; Bs[lc + 1][lr] = b0.y;
        Bs[lc + 2][lr] = b0.z; Bs[lc + 3][lr] = b0.w;
        __syncthreads();
        #pragma unroll
        for (int kk = 0; kk < 16; kk++) {
            float ar[8], br[4];
            #pragma unroll
            for (int i = 0; i < 8; i++) ar[i] = As[kk][ty * 8 + i];
            #pragma unroll
            for (int j = 0; j < 4; j++) br[j] = Bs[kk][tx * 4 + j];
            #pragma unroll
            for (int i = 0; i < 8; i++)
                #pragma unroll
                for (int j = 0; j < 4; j++)
                    acc[i][j] = fmaf(ar[i], br[j], acc[i][j]);
        }
        __syncthreads();
    }

    #pragma unroll
    for (int i = 0; i < 8; i++) {
        int m = m0 + ty * 8 + i;
        float bv = bias ? bias[m] : 0.f;
        #pragma unroll
        for (int j = 0; j < 4; j++) {
            int n = n0 + tx * 4 + j;
            float v = acc[i][j] + bv;
            if (flags & GF_GELU) v = geluf(v);
            if (res) {
                size_t ri = (flags & GF_RES_NMAJOR)
                    ? ((size_t)b * N + n) * (size_t)M + m
                    : ((size_t)b * M + m) * (size_t)N + n;
                v += res[ri];
            }
            size_t oi = (flags & GF_OUT_NMAJOR)
                ? ((size_t)b * N + n) * (size_t)M + m
                : ((size_t)b * M + m) * (size_t)N + n;
            C[oi] = v;
        }
    }
}

// ------------------------ depthwise 3x3 stride-2 ---------------------------
__global__ void dw_conv(const float* __restrict__ in, const float* __restrict__ w,
                        float* __restrict__ out, int Hi, int Ho)
{
    int idx = blockIdx.x * blockDim.x + threadIdx.x;
    int total = 4 * 128 * Ho * Ho;
    if (idx >= total) return;
    int ox = idx % Ho;
    int oy = (idx / Ho) % Ho;
    int c  = (idx / (Ho * Ho)) % 128;
    int g  = idx / (Ho * Ho * 128);
    const float* ip = in + (size_t)(g * 128 + c) * Hi * Hi;
    const float* wp = w + c * 9;
    float s = 0.f;
    #pragma unroll
    for (int ky = 0; ky < 3; ky++) {
        int iy = oy * 2 - 1 + ky;
        if (iy < 0 || iy >= Hi) continue;
        #pragma unroll
        for (int kx = 0; kx < 3; kx++) {
            int ix = ox * 2 - 1 + kx;
            if (ix < 0 || ix >= Hi) continue;
            s = fmaf(ip[iy * Hi + ix], wp[ky * 3 + kx], s);
        }
    }
    out[idx] = s;
}

// ------------------------- BN + GELU + transpose ---------------------------
__global__ void bn_gelu_t(const float* __restrict__ t3, const float* __restrict__ g,
                          const float* __restrict__ b, const float* __restrict__ m,
                          const float* __restrict__ v, float* __restrict__ oT)
{
    int idx = blockIdx.x * blockDim.x + threadIdx.x;
    if (idx >= 4 * 128 * 64) return;
    int wsp = idx % 64;
    int c   = (idx / 64) % 128;
    int gg  = idx / (64 * 128);
    float x = t3[idx];
    x = (x - m[c]) * rsqrtf(v[c] + 1e-5f) * g[c] + b[c];
    x = geluf(x);
    oT[(size_t)(gg * 64 + wsp) * 128 + c] = x;
}

// ------------------------- fused k/v deformable sampling -------------------
// kk = k_b + sum_g bilin(pk_g, grid_g);  vv likewise (conv commuted with the
// linear bilinear sample). One block per (b,w,r) point, 256 threads = out chans.
// pk/pv are pixel-major (g, pix, 256): every corner read is one 1KB coalesced
// row, L2-resident (16MB each). Output pixel-major [(b,w,r), c].
__global__ __launch_bounds__(256) void sample_kv(
    const float* __restrict__ offr, const float* __restrict__ pkT,
    const float* __restrict__ pvT, const float* __restrict__ kb,
    const float* __restrict__ vb, float* __restrict__ kkT,
    float* __restrict__ vvT)
{
    int blk = blockIdx.x;           // b*65536 + w*1024 + r
    int b = blk >> 16;
    int w = (blk >> 10) & 63;
    int r = blk & 1023;
    int ri2 = (r >> 5) << 1;
    int ci2 = (r & 31) << 1;
    int o = threadIdx.x;

    float ak = kb[o], av = vb[o];
    #pragma unroll
    for (int hg = 0; hg < 2; hg++) {
        int g = b * 2 + hg;
        float offRow = offr[(size_t)(g * 2048 + r) * 64 + w];
        float offCol = offr[(size_t)(g * 2048 + 1024 + r) * 64 + w];
        float rows = fmaf(tanhf(offRow), 0.984375f, (float)ri2);
        float cols = fmaf(tanhf(offCol), 0.984375f, (float)ci2);
        float r0f = floorf(rows), c0f = floorf(cols);
        float fr = rows - r0f, fc = cols - c0f;
        int r0 = (int)r0f, c0 = (int)c0f;
        const float* pk = pkT + (size_t)g * HWPIX * 256 + o;
        const float* pv = pvT + (size_t)g * HWPIX * 256 + o;
        float w00 = (1.f - fr) * (1.f - fc), w01 = (1.f - fr) * fc;
        float w10 = fr * (1.f - fc),         w11 = fr * fc;
        if (r0 >= 0 && r0 < 64) {
            if (c0 >= 0 && c0 < 64) {
                size_t p = (size_t)(r0 * 64 + c0) * 256;
                ak = fmaf(pk[p], w00, ak); av = fmaf(pv[p], w00, av);
            }
            if (c0 + 1 >= 0 && c0 + 1 < 64) {
                size_t p = (size_t)(r0 * 64 + c0 + 1) * 256;
                ak = fmaf(pk[p], w01, ak); av = fmaf(pv[p], w01, av);
            }
        }
        if (r0 + 1 >= 0 && r0 + 1 < 64) {
            if (c0 >= 0 && c0 < 64) {
                size_t p = (size_t)((r0 + 1) * 64 + c0) * 256;
                ak = fmaf(pk[p], w10, ak); av = fmaf(pv[p], w10, av);
            }
            if (c0 + 1 >= 0 && c0 + 1 < 64) {
                size_t p = (size_t)((r0 + 1) * 64 + c0 + 1) * 256;
                ak = fmaf(pk[p], w11, ak); av = fmaf(pv[p], w11, av);
            }
        }
    }
    size_t oi = (size_t)blk * 256 + o;
    kkT[oi] = ak;
    vvT[oi] = av;
}

// ------------------------------ attention ----------------------------------
// One block per (b, head, window). 256 threads = 64 queries x 4 r-lanes.
// kk/vv are pixel-major [(b,w,r),c]; tiles loaded as 128B channel rows and
// transposed into odd-padded smem (verified conflict-free per warp).
__global__ __launch_bounds__(256, 2) void attn_kernel(
    const float* __restrict__ qb, const float* __restrict__ kkT,
    const float* __restrict__ vvT, const float* __restrict__ pos,
    float* __restrict__ outT)
{
    __shared__ float wq_s[64][33];
    __shared__ float kk_s[32][65];
    __shared__ float vv_s[32][65];
    const int w = blockIdx.x, h = blockIdx.y, b = blockIdx.z;
    const int wh = w >> 3, wwx = w & 7;
    const int tid = threadIdx.x;

    for (int e = tid; e < 2048; e += 256) {
        int qq = e >> 5, c = e & 31;
        int yy = (wh << 3) + (qq >> 3), xx = (wwx << 3) + (qq & 7);
        wq_s[qq][c] = qb[(size_t)(b * 256 + h * 32 + c) * HWPIX + yy * 64 + xx] * 0.0625f;
    }
    __syncthreads();

    const int q = tid >> 2, lane = tid & 3;
    const int y = (wh << 3) + (q >> 3), x = (wwx << 3) + (q & 7);
    float wqr[32];
    #pragma unroll
    for (int c = 0; c < 32; c++) wqr[c] = wq_s[q][c];

    const float* posh = pos + h * 127 * 127 + (63 - y) * 127 + (63 - x);
    float m = -1e30f, s = 0.f;
    float acc[32];
    #pragma unroll
    for (int c = 0; c < 32; c++) acc[c] = 0.f;

    const size_t kvbase = ((size_t)b * NPIX_S + (size_t)w * 1024) * 256 + h * 32;
    const int rr_l = tid >> 2;          // 0..63 (row within tile)
    const int c8   = (tid & 3) << 3;    // 0,8,16,24 (channel sub-block)

    for (int r0 = 0; r0 < 1024; r0 += 64) {
        __syncthreads();
        {
            const float* kp = kkT + kvbase + (size_t)(r0 + rr_l) * 256 + c8;
            const float* vp = vvT + kvbase + (size_t)(r0 + rr_l) * 256 + c8;
            float4 k0 = *(const float4*)kp;  float4 k1 = *(const float4*)(kp + 4);
            float4 v0 = *(const float4*)vp;  float4 v1 = *(const float4*)(vp + 4);
            kk_s[c8    ][rr_l] = k0.x; kk_s[c8 + 1][rr_l] = k0.y;
            kk_s[c8 + 2][rr_l] = k0.z; kk_s[c8 + 3][rr_l] = k0.w;
            kk_s[c8 + 4][rr_l] = k1.x; kk_s[c8 + 5][rr_l] = k1.y;
            kk_s[c8 + 6][rr_l] = k1.z; kk_s[c8 + 7][rr_l] = k1.w;
            vv_s[c8    ][rr_l] = v0.x; vv_s[c8 + 1][rr_l] = v0.y;
            vv_s[c8 + 2][rr_l] = v0.z; vv_s[c8 + 3][rr_l] = v0.w;
            vv_s[c8 + 4][rr_l] = v1.x; vv_s[c8 + 5][rr_l] = v1.y;
            vv_s[c8 + 6][rr_l] = v1.z; vv_s[c8 + 7][rr_l] = v1.w;
        }
        __syncthreads();

        for (int t = 0; t < 16; t++) {
            int rr = (t << 2) + lane;
            int r  = r0 + rr;
            float sc = posh[((r >> 5) << 1) * 127 + ((r & 31) << 1)];
            #pragma unroll
            for (int c = 0; c < 32; c++) sc = fmaf(wqr[c], kk_s[c][rr], sc);
            if (sc > m) {
                float corr = fexp(m - sc);
                s = fmaf(s, corr, 1.0f);
                #pragma unroll
                for (int c = 0; c < 32; c++) acc[c] = fmaf(acc[c], corr, vv_s[c][rr]);
                m = sc;
            } else {
                float p = fexp(sc - m);
                s += p;
                #pragma unroll
                for (int c = 0; c < 32; c++) acc[c] = fmaf(p, vv_s[c][rr], acc[c]);
            }
        }
    }

    // merge 4 lanes of each query
    float M = m;
    M = fmaxf(M, __shfl_xor_sync(0xffffffffu, M, 1));
    M = fmaxf(M, __shfl_xor_sync(0xffffffffu, M, 2));
    float corr = fexp(m - M);
    s *= corr;
    s += __shfl_xor_sync(0xffffffffu, s, 1);
    s += __shfl_xor_sync(0xffffffffu, s, 2);
    #pragma unroll
    for (int c = 0; c < 32; c++) {
        float a = acc[c] * corr;
        a += __shfl_xor_sync(0xffffffffu, a, 1);
        a += __shfl_xor_sync(0xffffffffu, a, 2);
        acc[c] = a;
    }
    if (lane == 0) {
        float inv = 1.0f / s;
        float* op = outT + ((size_t)b * HWPIX + y * 64 + x) * 256 + h * 32;
        #pragma unroll
        for (int c = 0; c < 32; c++) op[c] = acc[c] * inv;
    }
}

// ------------------------------ launch -------------------------------------
extern "C" void kernel_launch(void* const* d_in, const int* in_sizes, int n_in,
                              void* d_out, int out_size)
{
    const float* x      = (const float*)d_in[0];
    const float* ln1_g  = (const float*)d_in[1];
    const float* ln1_b  = (const float*)d_in[2];
    const float* q_w    = (const float*)d_in[3];
    const float* q_b    = (const float*)d_in[4];
    const float* k_w    = (const float*)d_in[5];
    const float* k_b    = (const float*)d_in[6];
    const float* v_w    = (const float*)d_in[7];
    const float* v_b    = (const float*)d_in[8];
    const float* off1_w = (const float*)d_in[9];
    const float* off2_w = (const float*)d_in[10];
    const float* off3_w = (const float*)d_in[11];
    const float* bn_g   = (const float*)d_in[12];
    const float* bn_b   = (const float*)d_in[13];
    const float* bn_m   = (const float*)d_in[14];
    const float* bn_v   = (const float*)d_in[15];
    const float* off4_w = (const float*)d_in[16];
    const float* pos    = (const float*)d_in[17];
    const float* proj_w = (const float*)d_in[18];
    const float* proj_b = (const float*)d_in[19];
    const float* ln2_g  = (const float*)d_in[20];
    const float* ln2_b  = (const float*)d_in[21];
    const float* mlp_w1 = (const float*)d_in[22];
    const float* mlp_b1 = (const float*)d_in[23];
    const float* mlp_w2 = (const float*)d_in[24];
    const float* mlp_b2 = (const float*)d_in[25];
    float* out = (float*)d_out;

    float *xaT, *q, *t1, *t2, *t3, *oT, *offr, *pkT, *pvT, *kkb, *vvb, *attnT, *x2, *xmT, *hidT;
    cudaGetSymbolAddress((void**)&xaT,   g_xaT);
    cudaGetSymbolAddress((void**)&q,     g_q);
    cudaGetSymbolAddress((void**)&t1,    g_t1);
    cudaGetSymbolAddress((void**)&t2,    g_t2);
    cudaGetSymbolAddress((void**)&t3,    g_t3);
    cudaGetSymbolAddress((void**)&oT,    g_oT);
    cudaGetSymbolAddress((void**)&offr,  g_offr);
    cudaGetSymbolAddress((void**)&pkT,   g_pk);
    cudaGetSymbolAddress((void**)&pvT,   g_pv);
    cudaGetSymbolAddress((void**)&kkb,   g_kk);
    cudaGetSymbolAddress((void**)&vvb,   g_vv);
    cudaGetSymbolAddress((void**)&attnT, g_attnT);
    cudaGetSymbolAddress((void**)&x2,    g_x2);
    cudaGetSymbolAddress((void**)&xmT,   g_xmT);
    cudaGetSymbolAddress((void**)&hidT,  g_hidT);

    // 1. LN1: x (B,C,HW) C-major -> xaT pixel-major
    ln_kernel<<<8192, 256>>>(x, ln1_g, ln1_b, xaT,
                             (size_t)CDIM * HWPIX, (size_t)HWPIX, (size_t)1);

    // 2. q = q_w @ xa + q_b  -> C-major (B,256,4096)
    gemm_tn<<<dim3(HWPIX / 64, CDIM / 128, NB), 256>>>(
        q_w, CDIM, xaT, CDIM, (size_t)HWPIX * CDIM,
        q_b, nullptr, q, CDIM, HWPIX, CDIM, 0);

    // 3. offset path: 3x depthwise stride-2 convs (q viewed as (4,128,64,64))
    dw_conv<<<(4 * 128 * 32 * 32 + 255) / 256, 256>>>(q,  off1_w, t1, 64, 32);
    dw_conv<<<(4 * 128 * 16 * 16 + 255) / 256, 256>>>(t1, off2_w, t2, 32, 16);
    dw_conv<<<(4 * 128 *  8 *  8 + 255) / 256, 256>>>(t2, off3_w, t3, 16, 8);

    // 4. BN + GELU, transpose to pixel-major
    bn_gelu_t<<<(4 * 128 * 64 + 255) / 256, 256>>>(t3, bn_g, bn_b, bn_m, bn_v, oT);

    // 5. off4: (2048x128) @ (64x128)^T per group -> offr C-major (4,2048,64)
    gemm_tn<<<dim3(1, 2048 / 128, 4), 256>>>(
        off4_w, 128, oT, 128, (size_t)64 * 128,
        nullptr, nullptr, offr, 2048, 64, 128, 0);

    // 6a/6b. partial conv maps: pk[b,g] = k_w[:,g-chans] @ xa[g-chans]
    //        (grouped; out pixel-major (g,pix,256), bias added in sampler)
    gemm_tn<<<dim3(HWPIX / 64, 2, 4), 256>>>(
        k_w, CDIM, xaT, CDIM, 0,
        nullptr, nullptr, pkT, CDIM, HWPIX, GC, GF_GROUPED | GF_OUT_NMAJOR);
    gemm_tn<<<dim3(HWPIX / 64, 2, 4), 256>>>(
        v_w, CDIM, xaT, CDIM, 0,
        nullptr, nullptr, pvT, CDIM, HWPIX, GC, GF_GROUPED | GF_OUT_NMAJOR);

    // 7. fused deformable sampling of partial maps -> kk/vv pixel-major
    sample_kv<<<NB * NPIX_S, 256>>>(offr, pkT, pvT, k_b, v_b, kkb, vvb);

    // 8. windowed attention with rel-pos bias -> attnT pixel-major
    attn_kernel<<<dim3(NWIN, HEADS, NB), 256>>>(q, kkb, vvb, pos, attnT);

    // 9. proj + residual(x, C-major) -> x2 pixel-major
    gemm_tn<<<dim3(HWPIX / 64, CDIM / 128, NB), 256>>>(
        proj_w, CDIM, attnT, CDIM, (size_t)HWPIX * CDIM,
        proj_b, x, x2, CDIM, HWPIX, CDIM, GF_OUT_NMAJOR);

    // 10. LN2 on x2 (pixel-major) -> xmT pixel-major
    ln_kernel<<<8192, 256>>>(x2, ln2_g, ln2_b, xmT,
                             (size_t)HWPIX * CDIM, (size_t)1, (size_t)CDIM);

    // 11. mlp1 + gelu -> hidT pixel-major (B,4096,1024)
    gemm_tn<<<dim3(HWPIX / 64, MLPH / 128, NB), 256>>>(
        mlp_w1, CDIM, xmT, CDIM, (size_t)HWPIX * CDIM,
        mlp_b1, nullptr, hidT, MLPH, HWPIX, CDIM, GF_OUT_NMAJOR | GF_GELU);

    // 12. mlp2 + residual(x2, pixel-major) -> out C-major (B,256,64,64)
    gemm_tn<<<dim3(HWPIX / 64, CDIM / 128, NB), 256>>>(
        mlp_w2, MLPH, hidT, MLPH, (size_t)HWPIX * MLPH,
        mlp_b2, x2, out, CDIM, HWPIX, MLPH, GF_RES_NMAJOR);
}

// round 6
// speedup vs baseline: 1.4197x; 1.0489x over previous
#include <cuda_runtime.h>
#include <cuda_bf16.h>
#include <cstdint>
#include <cstddef>

// ---------------------------------------------------------------------------
// Problem constants
//   B=2, DIM=256, H=W=64, HEADS=8 (HC=32), HG=2 (GC=128), STRIDE=2,
//   WS=8 (NW=64 windows of WT=64 queries), RH=RW=32 (R=1024), MLP_HID=1024
// ---------------------------------------------------------------------------

#define NB      2
#define CDIM    256
#define HWPIX   4096            // 64*64
#define HEADS   8
#define HC      32
#define HG      2
#define GC      128
#define RPTS    1024            // R
#define NWIN    64              // NW
#define NPIX_S  65536           // NW * R
#define MLPH    1024

// ----------------------------- scratch ------------------------------------
__device__ float g_xaT [NB * HWPIX * CDIM];            // LN1 out, pixel-major
__device__ float g_q   [NB * CDIM * HWPIX];            // q conv out, C-major
__device__ float g_t1  [4 * 128 * 32 * 32];
__device__ float g_t2  [4 * 128 * 16 * 16];
__device__ float g_t3  [4 * 128 * 8 * 8];
__device__ float g_oT  [4 * 64 * 128];                 // bn+gelu out, pixel-major
__device__ float g_offr[4 * 2048 * 64];                // off4 out, C-major
__device__ float g_pk  [4 * HWPIX * CDIM];             // partial k maps, pixel-major
__device__ float g_pv  [4 * HWPIX * CDIM];             // partial v maps, pixel-major
__device__ float g_kk  [(size_t)NB * NPIX_S * CDIM];   // kk pixel-major [(b,w,r),c]
__device__ float g_vv  [(size_t)NB * NPIX_S * CDIM];   // vv pixel-major
__device__ float g_attnT[NB * HWPIX * CDIM];           // attention out, pixel-major
__device__ float g_x2  [NB * HWPIX * CDIM];            // x + proj, pixel-major
__device__ float g_xmT [NB * HWPIX * CDIM];            // LN2 out, pixel-major
__device__ float g_hidT[(size_t)NB * HWPIX * MLPH];    // mlp hidden, pixel-major

// ----------------------------- helpers ------------------------------------
__device__ __forceinline__ float geluf(float v) {
    return 0.5f * v * (1.0f + erff(v * 0.70710678118654752f));
}

// Packed f32x2 (Blackwell): FFMA2 doubles FMA-pipe FLOP rate; ptxas never
// emits it from C++ — only via PTX fma.rn.f32x2.
typedef unsigned long long u64p;
__device__ __forceinline__ u64p pack2(float lo, float hi) {
    u64p r;
    asm("mov.b64 %0, {%1, %2};" : "=l"(r) : "f"(lo), "f"(hi));
    return r;
}
__device__ __forceinline__ u64p fma2(u64p a, u64p b, u64p c) {
    u64p d;
    asm("fma.rn.f32x2 %0, %1, %2, %3;" : "=l"(d) : "l"(a), "l"(b), "l"(c));
    return d;
}
__device__ __forceinline__ float2 unpack2(u64p v) {
    float2 f;
    asm("mov.b64 {%0, %1}, %2;" : "=f"(f.x), "=f"(f.y) : "l"(v));
    return f;
}

// Fast exp on the FMA pipe (avoids MUFU EX2: rt_SMSP=8 -> ~140G/s chip ceiling
// vs 67M softmax exps). Degree-5 poly for 2^f, rel err ~8e-5.
__device__ __forceinline__ float fexp(float x) {
    float y = x * 1.4426950408889634f;
    y = fmaxf(y, -126.0f);
    float fi = floorf(y);
    float f = y - fi;
    float p = 0.0013333558f;
    p = fmaf(p, f, 0.0096181291f);
    p = fmaf(p, f, 0.0555041087f);
    p = fmaf(p, f, 0.2402264923f);
    p = fmaf(p, f, 0.6931471806f);
    p = fmaf(p, f, 1.0f);
    int e = (int)fi;
    return p * __int_as_float((e + 127) << 23);
}

// ----------------------------- LayerNorm -----------------------------------
__global__ __launch_bounds__(256) void ln_kernel(
    const float* __restrict__ in, const float* __restrict__ gam,
    const float* __restrict__ bet, float* __restrict__ outT,
    size_t bStride, size_t cStride, size_t pStride)
{
    int p  = blockIdx.x;            // 0..8191
    int b  = p >> 12;
    int hw = p & 4095;
    const float* ip = in + (size_t)b * bStride + (size_t)hw * pStride;
    int c = threadIdx.x;
    float v = ip[(size_t)c * cStride];
    float s1 = v, s2 = v * v;
    #pragma unroll
    for (int d = 16; d > 0; d >>= 1) {
        s1 += __shfl_xor_sync(0xffffffffu, s1, d);
        s2 += __shfl_xor_sync(0xffffffffu, s2, d);
    }
    __shared__ float sm1[8], sm2[8];
    __shared__ float mu_s, ri_s;
    int wid = c >> 5;
    if ((c & 31) == 0) { sm1[wid] = s1; sm2[wid] = s2; }
    __syncthreads();
    if (c == 0) {
        float t1 = 0.f, t2 = 0.f;
        #pragma unroll
        for (int i = 0; i < 8; i++) { t1 += sm1[i]; t2 += sm2[i]; }
        float mu  = t1 * (1.0f / 256.0f);
        float var = t2 * (1.0f / 256.0f) - mu * mu;
        mu_s = mu;
        ri_s = rsqrtf(var + 1e-5f);
    }
    __syncthreads();
    outT[(size_t)p * 256 + c] = (v - mu_s) * ri_s * gam[c] + bet[c];
}

// ----------------------------- GEMM (TN) ------------------------------------
// C[z] = A(MxK, lda) * B[z](NxK, ldb)^T (+bias)(gelu?)(+res?), flexible strides.
// FFMA2 inner loop: accumulators paired along M (A-pairs free via 8B LDS).
#define GF_OUT_NMAJOR 1
#define GF_RES_NMAJOR 2
#define GF_GELU       4
#define GF_GROUPED    8

__global__ __launch_bounds__(256) void gemm_tn(
    const float* __restrict__ A, int lda,
    const float* __restrict__ Bm, int ldb, size_t bZ,
    const float* __restrict__ bias, const float* __restrict__ res,
    float* __restrict__ C, int M, int N, int K, int flags)
{
    __shared__ float As[16][132];
    __shared__ float Bs[16][68];
    const int b  = blockIdx.z;
    const int m0 = blockIdx.y * 128;
    const int n0 = blockIdx.x * 64;
    const float* Ab = A;
    const float* Bb;
    if (flags & GF_GROUPED) {
        Ab = A + (b & 1) * 128;
        Bb = Bm + (size_t)(b >> 1) * ((size_t)HWPIX * 256) + (b & 1) * 128;
    } else {
        Bb = Bm + (size_t)b * bZ;
    }
    const int tid = threadIdx.x;
    const int lr = tid >> 2;          // 0..63
    const int lc = (tid & 3) << 2;    // 0,4,8,12
    const int ty = tid >> 4;          // 0..15
    const int tx = tid & 15;          // 0..15

    u64p acc2[4][4];
    #pragma unroll
    for (int i = 0; i < 4; i++)
        #pragma unroll
        for (int j = 0; j < 4; j++) acc2[i][j] = 0ULL;

    for (int k0 = 0; k0 < K; k0 += 16) {
        float4 a0 = *(const float4*)(Ab + (size_t)(m0 + lr)      * lda + k0 + lc);
        float4 a1 = *(const float4*)(Ab + (size_t)(m0 + lr + 64) * lda + k0 + lc);
        float4 b0 = *(const float4*)(Bb + (size_t)(n0 + lr)      * ldb + k0 + lc);
        As[lc    ][lr]      = a0.x; As[lc + 1][lr]      = a0.y;
        As[lc + 2][lr]      = a0.z; As[lc + 3][lr]      = a0.w;
        As[lc    ][lr + 64] = a1.x; As[lc + 1][lr + 64] = a1.y;
        As[lc + 2][lr + 64] = a1.z; As[lc + 3][lr + 64] = a1.w;
        Bs[lc    ][lr] = b0.x; Bs[lc + 1][lr] = b0.y;
        Bs[lc + 2][lr] = b0.z; Bs[lc + 3][lr] = b0.w;
        __syncthreads();
        #pragma unroll
        for (int kk = 0; kk < 16; kk++) {
            u64p a2[4];
            #pragma unroll
            for (int i2 = 0; i2 < 4; i2++)
                a2[i2] = *(const u64p*)&As[kk][ty * 8 + i2 * 2];
            float4 b4 = *(const float4*)&Bs[kk][tx * 4];
            u64p b2[4];
            b2[0] = pack2(b4.x, b4.x); b2[1] = pack2(b4.y, b4.y);
            b2[2] = pack2(b4.z, b4.z); b2[3] = pack2(b4.w, b4.w);
            #pragma unroll
            for (int i2 = 0; i2 < 4; i2++)
                #pragma unroll
                for (int j = 0; j < 4; j++)
                    acc2[i2][j] = fma2(a2[i2], b2[j], acc2[i2][j]);
        }
        __syncthreads();
    }

    #pragma unroll
    for (int i2 = 0; i2 < 4; i2++) {
        int mA = m0 + ty * 8 + i2 * 2;
        float bvA = bias ? bias[mA] : 0.f;
        float bvB = bias ? bias[mA + 1] : 0.f;
        #pragma unroll
        for (int j = 0; j < 4; j++) {
            int n = n0 + tx * 4 + j;
            float2 u = unpack2(acc2[i2][j]);
            float vA = u.x + bvA;
            float vB = u.y + bvB;
            if (flags & GF_GELU) { vA = geluf(vA); vB = geluf(vB); }
            if (res) {
                if (flags & GF_RES_NMAJOR) {
                    const float* rp = res + ((size_t)b * N + n) * (size_t)M + mA;
                    vA += rp[0]; vB += rp[1];
                } else {
                    vA += res[((size_t)b * M + mA)     * (size_t)N + n];
                    vB += res[((size_t)b * M + mA + 1) * (size_t)N + n];
                }
            }
            if (flags & GF_OUT_NMAJOR) {
                float* cp = C + ((size_t)b * N + n) * (size_t)M + mA;
                cp[0] = vA; cp[1] = vB;
            } else {
                C[((size_t)b * M + mA)     * (size_t)N + n] = vA;
                C[((size_t)b * M + mA + 1) * (size_t)N + n] = vB;
            }
        }
    }
}

// ------------------------ depthwise 3x3 stride-2 ---------------------------
__global__ void dw_conv(const float* __restrict__ in, const float* __restrict__ w,
                        float* __restrict__ out, int Hi, int Ho)
{
    int idx = blockIdx.x * blockDim.x + threadIdx.x;
    int total = 4 * 128 * Ho * Ho;
    if (idx >= total) return;
    int ox = idx % Ho;
    int oy = (idx / Ho) % Ho;
    int c  = (idx / (Ho * Ho)) % 128;
    int g  = idx / (Ho * Ho * 128);
    const float* ip = in + (size_t)(g * 128 + c) * Hi * Hi;
    const float* wp = w + c * 9;
    float s = 0.f;
    #pragma unroll
    for (int ky = 0; ky < 3; ky++) {
        int iy = oy * 2 - 1 + ky;
        if (iy < 0 || iy >= Hi) continue;
        #pragma unroll
        for (int kx = 0; kx < 3; kx++) {
            int ix = ox * 2 - 1 + kx;
            if (ix < 0 || ix >= Hi) continue;
            s = fmaf(ip[iy * Hi + ix], wp[ky * 3 + kx], s);
        }
    }
    out[idx] = s;
}

// ------------------------- BN + GELU + transpose ---------------------------
__global__ void bn_gelu_t(const float* __restrict__ t3, const float* __restrict__ g,
                          const float* __restrict__ b, const float* __restrict__ m,
                          const float* __restrict__ v, float* __restrict__ oT)
{
    int idx = blockIdx.x * blockDim.x + threadIdx.x;
    if (idx >= 4 * 128 * 64) return;
    int wsp = idx % 64;
    int c   = (idx / 64) % 128;
    int gg  = idx / (64 * 128);
    float x = t3[idx];
    x = (x - m[c]) * rsqrtf(v[c] + 1e-5f) * g[c] + b[c];
    x = geluf(x);
    oT[(size_t)(gg * 64 + wsp) * 128 + c] = x;
}

// ------------------------- fused k/v deformable sampling -------------------
__global__ __launch_bounds__(256) void sample_kv(
    const float* __restrict__ offr, const float* __restrict__ pkT,
    const float* __restrict__ pvT, const float* __restrict__ kb,
    const float* __restrict__ vb, float* __restrict__ kkT,
    float* __restrict__ vvT)
{
    int blk = blockIdx.x;           // b*65536 + w*1024 + r
    int b = blk >> 16;
    int w = (blk >> 10) & 63;
    int r = blk & 1023;
    int ri2 = (r >> 5) << 1;
    int ci2 = (r & 31) << 1;
    int o = threadIdx.x;

    float ak = kb[o], av = vb[o];
    #pragma unroll
    for (int hg = 0; hg < 2; hg++) {
        int g = b * 2 + hg;
        float offRow = offr[(size_t)(g * 2048 + r) * 64 + w];
        float offCol = offr[(size_t)(g * 2048 + 1024 + r) * 64 + w];
        float rows = fmaf(tanhf(offRow), 0.984375f, (float)ri2);
        float cols = fmaf(tanhf(offCol), 0.984375f, (float)ci2);
        float r0f = floorf(rows), c0f = floorf(cols);
        float fr = rows - r0f, fc = cols - c0f;
        int r0 = (int)r0f, c0 = (int)c0f;
        const float* pk = pkT + (size_t)g * HWPIX * 256 + o;
        const float* pv = pvT + (size_t)g * HWPIX * 256 + o;
        float w00 = (1.f - fr) * (1.f - fc), w01 = (1.f - fr) * fc;
        float w10 = fr * (1.f - fc),         w11 = fr * fc;
        if (r0 >= 0 && r0 < 64) {
            if (c0 >= 0 && c0 < 64) {
                size_t p = (size_t)(r0 * 64 + c0) * 256;
                ak = fmaf(pk[p], w00, ak); av = fmaf(pv[p], w00, av);
            }
            if (c0 + 1 >= 0 && c0 + 1 < 64) {
                size_t p = (size_t)(r0 * 64 + c0 + 1) * 256;
                ak = fmaf(pk[p], w01, ak); av = fmaf(pv[p], w01, av);
            }
        }
        if (r0 + 1 >= 0 && r0 + 1 < 64) {
            if (c0 >= 0 && c0 < 64) {
                size_t p = (size_t)((r0 + 1) * 64 + c0) * 256;
                ak = fmaf(pk[p], w10, ak); av = fmaf(pv[p], w10, av);
            }
            if (c0 + 1 >= 0 && c0 + 1 < 64) {
                size_t p = (size_t)((r0 + 1) * 64 + c0 + 1) * 256;
                ak = fmaf(pk[p], w11, ak); av = fmaf(pv[p], w11, av);
            }
        }
    }
    size_t oi = (size_t)blk * 256 + o;
    kkT[oi] = ak;
    vvT[oi] = av;
}

// ------------------------------ attention ----------------------------------
// One block per (b, head, window). 256 threads = 64 queries x 4 r-lanes.
// kk/vv smem row-major [r][c] (pad 36): compute loop uses 8B channel-pair
// loads + FFMA2 (packed f32x2) for both QK and PV.
__global__ __launch_bounds__(256, 2) void attn_kernel(
    const float* __restrict__ qb, const float* __restrict__ kkT,
    const float* __restrict__ vvT, const float* __restrict__ pos,
    float* __restrict__ outT)
{
    __shared__ float wq_s[64][33];
    __shared__ float kk_s[64][36];
    __shared__ float vv_s[64][36];
    const int w = blockIdx.x, h = blockIdx.y, b = blockIdx.z;
    const int wh = w >> 3, wwx = w & 7;
    const int tid = threadIdx.x;

    for (int e = tid; e < 2048; e += 256) {
        int qq = e >> 5, c = e & 31;
        int yy = (wh << 3) + (qq >> 3), xx = (wwx << 3) + (qq & 7);
        wq_s[qq][c] = qb[(size_t)(b * 256 + h * 32 + c) * HWPIX + yy * 64 + xx] * 0.0625f;
    }
    __syncthreads();

    const int q = tid >> 2, lane = tid & 3;
    const int y = (wh << 3) + (q >> 3), x = (wwx << 3) + (q & 7);
    u64p wq2[16];
    #pragma unroll
    for (int c2 = 0; c2 < 16; c2++)
        wq2[c2] = pack2(wq_s[q][c2 * 2], wq_s[q][c2 * 2 + 1]);

    const float* posh = pos + h * 127 * 127 + (63 - y) * 127 + (63 - x);
    float m = -1e30f, s = 0.f;
    u64p acc2[16];
    #pragma unroll
    for (int c2 = 0; c2 < 16; c2++) acc2[c2] = 0ULL;

    const size_t kvbase = ((size_t)b * NPIX_S + (size_t)w * 1024) * 256 + h * 32;
    const int rr_l = tid >> 2;          // 0..63 (row within tile)
    const int c8   = (tid & 3) << 3;    // 0,8,16,24 (channel sub-block)

    for (int r0 = 0; r0 < 1024; r0 += 64) {
        __syncthreads();
        {
            const float* kp = kkT + kvbase + (size_t)(r0 + rr_l) * 256 + c8;
            const float* vp = vvT + kvbase + (size_t)(r0 + rr_l) * 256 + c8;
            float4 k0 = *(const float4*)kp;  float4 k1 = *(const float4*)(kp + 4);
            float4 v0 = *(const float4*)vp;  float4 v1 = *(const float4*)(vp + 4);
            *(float4*)&kk_s[rr_l][c8]     = k0;
            *(float4*)&kk_s[rr_l][c8 + 4] = k1;
            *(float4*)&vv_s[rr_l][c8]     = v0;
            *(float4*)&vv_s[rr_l][c8 + 4] = v1;
        }
        __syncthreads();

        #pragma unroll 4
        for (int t = 0; t < 16; t++) {
            int rr = (t << 2) + lane;
            int r  = r0 + rr;
            float bv = posh[((r >> 5) << 1) * 127 + ((r & 31) << 1)];
            const u64p* krow = (const u64p*)&kk_s[rr][0];
            u64p sc2 = 0ULL;
            #pragma unroll
            for (int c2 = 0; c2 < 16; c2++) sc2 = fma2(wq2[c2], krow[c2], sc2);
            float2 u = unpack2(sc2);
            float sc = u.x + u.y + bv;
            const u64p* vrow = (const u64p*)&vv_s[rr][0];
            if (sc > m) {
                float corr = fexp(m - sc);
                s = fmaf(s, corr, 1.0f);
                u64p cp2 = pack2(corr, corr);
                #pragma unroll
                for (int c2 = 0; c2 < 16; c2++)
                    acc2[c2] = fma2(acc2[c2], cp2, vrow[c2]);
                m = sc;
            } else {
                float p = fexp(sc - m);
                s += p;
                u64p p2 = pack2(p, p);
                #pragma unroll
                for (int c2 = 0; c2 < 16; c2++)
                    acc2[c2] = fma2(p2, vrow[c2], acc2[c2]);
            }
        }
    }

    // merge 4 lanes of each query
    float M = m;
    M = fmaxf(M, __shfl_xor_sync(0xffffffffu, M, 1));
    M = fmaxf(M, __shfl_xor_sync(0xffffffffu, M, 2));
    float corr = fexp(m - M);
    s *= corr;
    s += __shfl_xor_sync(0xffffffffu, s, 1);
    s += __shfl_xor_sync(0xffffffffu, s, 2);
    float accs[32];
    #pragma unroll
    for (int c2 = 0; c2 < 16; c2++) {
        float2 u = unpack2(acc2[c2]);
        accs[c2 * 2] = u.x; accs[c2 * 2 + 1] = u.y;
    }
    #pragma unroll
    for (int c = 0; c < 32; c++) {
        float a = accs[c] * corr;
        a += __shfl_xor_sync(0xffffffffu, a, 1);
        a += __shfl_xor_sync(0xffffffffu, a, 2);
        accs[c] = a;
    }
    if (lane == 0) {
        float inv = 1.0f / s;
        float* op = outT + ((size_t)b * HWPIX + y * 64 + x) * 256 + h * 32;
        #pragma unroll
        for (int c = 0; c < 32; c++) op[c] = accs[c] * inv;
    }
}

// ------------------------------ launch -------------------------------------
extern "C" void kernel_launch(void* const* d_in, const int* in_sizes, int n_in,
                              void* d_out, int out_size)
{
    const float* x      = (const float*)d_in[0];
    const float* ln1_g  = (const float*)d_in[1];
    const float* ln1_b  = (const float*)d_in[2];
    const float* q_w    = (const float*)d_in[3];
    const float* q_b    = (const float*)d_in[4];
    const float* k_w    = (const float*)d_in[5];
    const float* k_b    = (const float*)d_in[6];
    const float* v_w    = (const float*)d_in[7];
    const float* v_b    = (const float*)d_in[8];
    const float* off1_w = (const float*)d_in[9];
    const float* off2_w = (const float*)d_in[10];
    const float* off3_w = (const float*)d_in[11];
    const float* bn_g   = (const float*)d_in[12];
    const float* bn_b   = (const float*)d_in[13];
    const float* bn_m   = (const float*)d_in[14];
    const float* bn_v   = (const float*)d_in[15];
    const float* off4_w = (const float*)d_in[16];
    const float* pos    = (const float*)d_in[17];
    const float* proj_w = (const float*)d_in[18];
    const float* proj_b = (const float*)d_in[19];
    const float* ln2_g  = (const float*)d_in[20];
    const float* ln2_b  = (const float*)d_in[21];
    const float* mlp_w1 = (const float*)d_in[22];
    const float* mlp_b1 = (const float*)d_in[23];
    const float* mlp_w2 = (const float*)d_in[24];
    const float* mlp_b2 = (const float*)d_in[25];
    float* out = (float*)d_out;

    float *xaT, *q, *t1, *t2, *t3, *oT, *offr, *pkT, *pvT, *kkb, *vvb, *attnT, *x2, *xmT, *hidT;
    cudaGetSymbolAddress((void**)&xaT,   g_xaT);
    cudaGetSymbolAddress((void**)&q,     g_q);
    cudaGetSymbolAddress((void**)&t1,    g_t1);
    cudaGetSymbolAddress((void**)&t2,    g_t2);
    cudaGetSymbolAddress((void**)&t3,    g_t3);
    cudaGetSymbolAddress((void**)&oT,    g_oT);
    cudaGetSymbolAddress((void**)&offr,  g_offr);
    cudaGetSymbolAddress((void**)&pkT,   g_pk);
    cudaGetSymbolAddress((void**)&pvT,   g_pv);
    cudaGetSymbolAddress((void**)&kkb,   g_kk);
    cudaGetSymbolAddress((void**)&vvb,   g_vv);
    cudaGetSymbolAddress((void**)&attnT, g_attnT);
    cudaGetSymbolAddress((void**)&x2,    g_x2);
    cudaGetSymbolAddress((void**)&xmT,   g_xmT);
    cudaGetSymbolAddress((void**)&hidT,  g_hidT);

    // 1. LN1: x (B,C,HW) C-major -> xaT pixel-major
    ln_kernel<<<8192, 256>>>(x, ln1_g, ln1_b, xaT,
                             (size_t)CDIM * HWPIX, (size_t)HWPIX, (size_t)1);

    // 2. q = q_w @ xa + q_b  -> C-major (B,256,4096)
    gemm_tn<<<dim3(HWPIX / 64, CDIM / 128, NB), 256>>>(
        q_w, CDIM, xaT, CDIM, (size_t)HWPIX * CDIM,
        q_b, nullptr, q, CDIM, HWPIX, CDIM, 0);

    // 3. offset path: 3x depthwise stride-2 convs (q viewed as (4,128,64,64))
    dw_conv<<<(4 * 128 * 32 * 32 + 255) / 256, 256>>>(q,  off1_w, t1, 64, 32);
    dw_conv<<<(4 * 128 * 16 * 16 + 255) / 256, 256>>>(t1, off2_w, t2, 32, 16);
    dw_conv<<<(4 * 128 *  8 *  8 + 255) / 256, 256>>>(t2, off3_w, t3, 16, 8);

    // 4. BN + GELU, transpose to pixel-major
    bn_gelu_t<<<(4 * 128 * 64 + 255) / 256, 256>>>(t3, bn_g, bn_b, bn_m, bn_v, oT);

    // 5. off4: (2048x128) @ (64x128)^T per group -> offr C-major (4,2048,64)
    gemm_tn<<<dim3(1, 2048 / 128, 4), 256>>>(
        off4_w, 128, oT, 128, (size_t)64 * 128,
        nullptr, nullptr, offr, 2048, 64, 128, 0);

    // 6a/6b. partial conv maps: pk[b,g] = k_w[:,g-chans] @ xa[g-chans]
    gemm_tn<<<dim3(HWPIX / 64, 2, 4), 256>>>(
        k_w, CDIM, xaT, CDIM, 0,
        nullptr, nullptr, pkT, CDIM, HWPIX, GC, GF_GROUPED | GF_OUT_NMAJOR);
    gemm_tn<<<dim3(HWPIX / 64, 2, 4), 256>>>(
        v_w, CDIM, xaT, CDIM, 0,
        nullptr, nullptr, pvT, CDIM, HWPIX, GC, GF_GROUPED | GF_OUT_NMAJOR);

    // 7. fused deformable sampling of partial maps -> kk/vv pixel-major
    sample_kv<<<NB * NPIX_S, 256>>>(offr, pkT, pvT, k_b, v_b, kkb, vvb);

    // 8. windowed attention with rel-pos bias -> attnT pixel-major
    attn_kernel<<<dim3(NWIN, HEADS, NB), 256>>>(q, kkb, vvb, pos, attnT);

    // 9. proj + residual(x, C-major) -> x2 pixel-major
    gemm_tn<<<dim3(HWPIX / 64, CDIM / 128, NB), 256>>>(
        proj_w, CDIM, attnT, CDIM, (size_t)HWPIX * CDIM,
        proj_b, x, x2, CDIM, HWPIX, CDIM, GF_OUT_NMAJOR);

    // 10. LN2 on x2 (pixel-major) -> xmT pixel-major
    ln_kernel<<<8192, 256>>>(x2, ln2_g, ln2_b, xmT,
                             (size_t)HWPIX * CDIM, (size_t)1, (size_t)CDIM);

    // 11. mlp1 + gelu -> hidT pixel-major (B,4096,1024)
    gemm_tn<<<dim3(HWPIX / 64, MLPH / 128, NB), 256>>>(
        mlp_w1, CDIM, xmT, CDIM, (size_t)HWPIX * CDIM,
        mlp_b1, nullptr, hidT, MLPH, HWPIX, CDIM, GF_OUT_NMAJOR | GF_GELU);

    // 12. mlp2 + residual(x2, pixel-major) -> out C-major (B,256,64,64)
    gemm_tn<<<dim3(HWPIX / 64, CDIM / 128, NB), 256>>>(
        mlp_w2, MLPH, hidT, MLPH, (size_t)HWPIX * MLPH,
        mlp_b2, x2, out, CDIM, HWPIX, MLPH, GF_RES_NMAJOR);
}

// round 8
// speedup vs baseline: 1.7210x; 1.2122x over previous
#include <cuda_runtime.h>
#include <cuda_bf16.h>
#include <cstdint>
#include <cstddef>

// ---------------------------------------------------------------------------
// Problem constants
//   B=2, DIM=256, H=W=64, HEADS=8 (HC=32), HG=2 (GC=128), STRIDE=2,
//   WS=8 (NW=64 windows of WT=64 queries), RH=RW=32 (R=1024), MLP_HID=1024
// ---------------------------------------------------------------------------

#define NB      2
#define CDIM    256
#define HWPIX   4096            // 64*64
#define HEADS   8
#define HC      32
#define HG      2
#define GC      128
#define RPTS    1024            // R
#define NWIN    64              // NW
#define NPIX_S  65536           // NW * R
#define MLPH    1024

// ----------------------------- scratch ------------------------------------
__device__ float g_xaT [NB * HWPIX * CDIM];            // LN1 out, pixel-major
__device__ float g_q   [NB * CDIM * HWPIX];            // q conv out, C-major
__device__ float g_t1  [4 * 128 * 32 * 32];
__device__ float g_t2  [4 * 128 * 16 * 16];
__device__ float g_t3  [4 * 128 * 8 * 8];
__device__ float g_oT  [4 * 64 * 128];                 // bn+gelu out, pixel-major
__device__ float g_offr[4 * 2048 * 64];                // off4 out, C-major
__device__ float g_pk  [4 * HWPIX * CDIM];             // partial k maps, pixel-major
__device__ float g_pv  [4 * HWPIX * CDIM];             // partial v maps, pixel-major
__device__ float g_kk  [(size_t)NB * NPIX_S * CDIM];   // kk pixel-major [(b,w,r),c]
__device__ float g_vv  [(size_t)NB * NPIX_S * CDIM];   // vv pixel-major
__device__ float g_attnT[NB * HWPIX * CDIM];           // attention out, pixel-major
__device__ float g_x2  [NB * HWPIX * CDIM];            // x + proj, pixel-major
__device__ float g_xmT [NB * HWPIX * CDIM];            // LN2 out, pixel-major
__device__ float g_hidT[(size_t)NB * HWPIX * MLPH];    // mlp hidden, pixel-major

// ----------------------------- helpers ------------------------------------
__device__ __forceinline__ float geluf(float v) {
    return 0.5f * v * (1.0f + erff(v * 0.70710678118654752f));
}

// tf32 round-to-nearest conversion (kept in f32 container).
__device__ __forceinline__ float to_tf32(float x) {
    uint32_t u;
    asm("cvt.rna.tf32.f32 %0, %1;" : "=r"(u) : "f"(x));
    return __uint_as_float(u);
}

// m16n8k8 TF32 tensor-core MMA (fp32 accumulate).
__device__ __forceinline__ void mma_tf32(float* d, const uint32_t* a, const uint32_t* b) {
    asm volatile(
        "mma.sync.aligned.m16n8k8.row.col.f32.tf32.tf32.f32 "
        "{%0,%1,%2,%3}, {%4,%5,%6,%7}, {%8,%9}, {%0,%1,%2,%3};"
        : "+f"(d[0]), "+f"(d[1]), "+f"(d[2]), "+f"(d[3])
        : "r"(a[0]), "r"(a[1]), "r"(a[2]), "r"(a[3]), "r"(b[0]), "r"(b[1]));
}

// Packed f32x2 helpers (attention inner loop).
typedef unsigned long long u64p;
__device__ __forceinline__ u64p pack2(float lo, float hi) {
    u64p r;
    asm("mov.b64 %0, {%1, %2};" : "=l"(r) : "f"(lo), "f"(hi));
    return r;
}
__device__ __forceinline__ u64p fma2(u64p a, u64p b, u64p c) {
    u64p d;
    asm("fma.rn.f32x2 %0, %1, %2, %3;" : "=l"(d) : "l"(a), "l"(b), "l"(c));
    return d;
}
__device__ __forceinline__ float2 unpack2(u64p v) {
    float2 f;
    asm("mov.b64 {%0, %1}, %2;" : "=f"(f.x), "=f"(f.y) : "l"(v));
    return f;
}

// Fast exp on the FMA pipe. Degree-5 poly for 2^f, rel err ~8e-5.
__device__ __forceinline__ float fexp(float x) {
    float y = x * 1.4426950408889634f;
    y = fmaxf(y, -126.0f);
    float fi = floorf(y);
    float f = y - fi;
    float p = 0.0013333558f;
    p = fmaf(p, f, 0.0096181291f);
    p = fmaf(p, f, 0.0555041087f);
    p = fmaf(p, f, 0.2402264923f);
    p = fmaf(p, f, 0.6931471806f);
    p = fmaf(p, f, 1.0f);
    int e = (int)fi;
    return p * __int_as_float((e + 127) << 23);
}

// ----------------------------- LayerNorm -----------------------------------
__global__ __launch_bounds__(256) void ln_kernel(
    const float* __restrict__ in, const float* __restrict__ gam,
    const float* __restrict__ bet, float* __restrict__ outT,
    size_t bStride, size_t cStride, size_t pStride)
{
    int p  = blockIdx.x;            // 0..8191
    int b  = p >> 12;
    int hw = p & 4095;
    const float* ip = in + (size_t)b * bStride + (size_t)hw * pStride;
    int c = threadIdx.x;
    float v = ip[(size_t)c * cStride];
    float s1 = v, s2 = v * v;
    #pragma unroll
    for (int d = 16; d > 0; d >>= 1) {
        s1 += __shfl_xor_sync(0xffffffffu, s1, d);
        s2 += __shfl_xor_sync(0xffffffffu, s2, d);
    }
    __shared__ float sm1[8], sm2[8];
    __shared__ float mu_s, ri_s;
    int wid = c >> 5;
    if ((c & 31) == 0) { sm1[wid] = s1; sm2[wid] = s2; }
    __syncthreads();
    if (c == 0) {
        float t1 = 0.f, t2 = 0.f;
        #pragma unroll
        for (int i = 0; i < 8; i++) { t1 += sm1[i]; t2 += sm2[i]; }
        float mu  = t1 * (1.0f / 256.0f);
        float var = t2 * (1.0f / 256.0f) - mu * mu;
        mu_s = mu;
        ri_s = rsqrtf(var + 1e-5f);
    }
    __syncthreads();
    outT[(size_t)p * 256 + c] = (v - mu_s) * ri_s * gam[c] + bet[c];
}

// ----------------------------- GEMM (TN, TF32 tensor core) ------------------
// C[z] = A(MxK, lda) * B[z](NxK, ldb)^T (+bias)(gelu?)(+res?).
// BM=128, BN=64, BK=32; 8 warps (4 m x 2 n), each 32x32 via 2x4 m16n8k8 frags.
// Smem [m][k] pad 36 -> fragment LDS verified conflict-free (bank=4g+tg).
#define GF_OUT_NMAJOR 1
#define GF_RES_NMAJOR 2
#define GF_GELU       4
#define GF_GROUPED    8

__global__ __launch_bounds__(256) void gemm_tn(
    const float* __restrict__ A, int lda,
    const float* __restrict__ Bm, int ldb, size_t bZ,
    const float* __restrict__ bias, const float* __restrict__ res,
    float* __restrict__ C, int M, int N, int K, int flags)
{
    __shared__ float As[128][36];
    __shared__ float Bs[64][36];
    const int b  = blockIdx.z;
    const int m0 = blockIdx.y * 128;
    const int n0 = blockIdx.x * 64;
    const float* Ab = A;
    const float* Bb;
    if (flags & GF_GROUPED) {
        Ab = A + (b & 1) * 128;
        Bb = Bm + (size_t)(b >> 1) * ((size_t)HWPIX * 256) + (b & 1) * 128;
    } else {
        Bb = Bm + (size_t)b * bZ;
    }
    const int tid  = threadIdx.x;
    const int warp = tid >> 5, lane = tid & 31;
    const int g = lane >> 2, tg = lane & 3;
    const int wm = warp & 3;        // 0..3 -> 32-row m block
    const int wn = warp >> 2;       // 0..1 -> 32-col n block

    float acc[2][4][4];
    #pragma unroll
    for (int mi = 0; mi < 2; mi++)
        #pragma unroll
        for (int nj = 0; nj < 4; nj++)
            #pragma unroll
            for (int e = 0; e < 4; e++) acc[mi][nj][e] = 0.f;

    for (int k0 = 0; k0 < K; k0 += 32) {
        // stage A: 128x32 = 1024 float4, 4 per thread (tf32-converted)
        #pragma unroll
        for (int i = 0; i < 4; i++) {
            int e = tid + i * 256;
            int row = e >> 3, c4 = (e & 7) << 2;
            float4 a = *(const float4*)(Ab + (size_t)(m0 + row) * lda + k0 + c4);
            As[row][c4    ] = to_tf32(a.x);
            As[row][c4 + 1] = to_tf32(a.y);
            As[row][c4 + 2] = to_tf32(a.z);
            As[row][c4 + 3] = to_tf32(a.w);
        }
        // stage B: 64x32 = 512 float4, 2 per thread
        #pragma unroll
        for (int i = 0; i < 2; i++) {
            int e = tid + i * 256;
            int row = e >> 3, c4 = (e & 7) << 2;
            float4 v = *(const float4*)(Bb + (size_t)(n0 + row) * ldb + k0 + c4);
            Bs[row][c4    ] = to_tf32(v.x);
            Bs[row][c4 + 1] = to_tf32(v.y);
            Bs[row][c4 + 2] = to_tf32(v.z);
            Bs[row][c4 + 3] = to_tf32(v.w);
        }
        __syncthreads();

        #pragma unroll
        for (int kk = 0; kk < 4; kk++) {
            int kb = kk * 8;
            uint32_t af[2][4], bf[4][2];
            #pragma unroll
            for (int mi = 0; mi < 2; mi++) {
                int mr = wm * 32 + mi * 16;
                af[mi][0] = __float_as_uint(As[mr + g    ][kb + tg    ]);
                af[mi][1] = __float_as_uint(As[mr + g + 8][kb + tg    ]);
                af[mi][2] = __float_as_uint(As[mr + g    ][kb + tg + 4]);
                af[mi][3] = __float_as_uint(As[mr + g + 8][kb + tg + 4]);
            }
            #pragma unroll
            for (int nj = 0; nj < 4; nj++) {
                int nr = wn * 32 + nj * 8;
                bf[nj][0] = __float_as_uint(Bs[nr + g][kb + tg    ]);
                bf[nj][1] = __float_as_uint(Bs[nr + g][kb + tg + 4]);
            }
            #pragma unroll
            for (int mi = 0; mi < 2; mi++)
                #pragma unroll
                for (int nj = 0; nj < 4; nj++)
                    mma_tf32(acc[mi][nj], af[mi], bf[nj]);
        }
        __syncthreads();
    }

    // epilogue: c0,c1 = (row g, cols 2tg,2tg+1); c2,c3 = (row g+8, same cols)
    #pragma unroll
    for (int mi = 0; mi < 2; mi++) {
        #pragma unroll
        for (int nj = 0; nj < 4; nj++) {
            int nc = n0 + wn * 32 + nj * 8 + tg * 2;
            #pragma unroll
            for (int e = 0; e < 4; e++) {
                int m = m0 + wm * 32 + mi * 16 + g + (e >> 1) * 8;
                int n = nc + (e & 1);
                float v = acc[mi][nj][e];
                if (bias) v += bias[m];
                if (flags & GF_GELU) v = geluf(v);
                if (res) {
                    size_t ri = (flags & GF_RES_NMAJOR)
                        ? ((size_t)b * N + n) * (size_t)M + m
                        : ((size_t)b * M + m) * (size_t)N + n;
                    v += res[ri];
                }
                size_t oi = (flags & GF_OUT_NMAJOR)
                    ? ((size_t)b * N + n) * (size_t)M + m
                    : ((size_t)b * M + m) * (size_t)N + n;
                C[oi] = v;
            }
        }
    }
}

// ------------------------ depthwise 3x3 stride-2 ---------------------------
__global__ void dw_conv(const float* __restrict__ in, const float* __restrict__ w,
                        float* __restrict__ out, int Hi, int Ho)
{
    int idx = blockIdx.x * blockDim.x + threadIdx.x;
    int total = 4 * 128 * Ho * Ho;
    if (idx >= total) return;
    int ox = idx % Ho;
    int oy = (idx / Ho) % Ho;
    int c  = (idx / (Ho * Ho)) % 128;
    int g  = idx / (Ho * Ho * 128);
    const float* ip = in + (size_t)(g * 128 + c) * Hi * Hi;
    const float* wp = w + c * 9;
    float s = 0.f;
    #pragma unroll
    for (int ky = 0; ky < 3; ky++) {
        int iy = oy * 2 - 1 + ky;
        if (iy < 0 || iy >= Hi) continue;
        #pragma unroll
        for (int kx = 0; kx < 3; kx++) {
            int ix = ox * 2 - 1 + kx;
            if (ix < 0 || ix >= Hi) continue;
            s = fmaf(ip[iy * Hi + ix], wp[ky * 3 + kx], s);
        }
    }
    out[idx] = s;
}

// ------------------------- BN + GELU + transpose ---------------------------
__global__ void bn_gelu_t(const float* __restrict__ t3, const float* __restrict__ g,
                          const float* __restrict__ b, const float* __restrict__ m,
                          const float* __restrict__ v, float* __restrict__ oT)
{
    int idx = blockIdx.x * blockDim.x + threadIdx.x;
    if (idx >= 4 * 128 * 64) return;
    int wsp = idx % 64;
    int c   = (idx / 64) % 128;
    int gg  = idx / (64 * 128);
    float x = t3[idx];
    x = (x - m[c]) * rsqrtf(v[c] + 1e-5f) * g[c] + b[c];
    x = geluf(x);
    oT[(size_t)(gg * 64 + wsp) * 128 + c] = x;
}

// ------------------------- fused k/v deformable sampling -------------------
__global__ __launch_bounds__(256) void sample_kv(
    const float* __restrict__ offr, const float* __restrict__ pkT,
    const float* __restrict__ pvT, const float* __restrict__ kb,
    const float* __restrict__ vb, float* __restrict__ kkT,
    float* __restrict__ vvT)
{
    int blk = blockIdx.x;           // b*65536 + w*1024 + r
    int b = blk >> 16;
    int w = (blk >> 10) & 63;
    int r = blk & 1023;
    int ri2 = (r >> 5) << 1;
    int ci2 = (r & 31) << 1;
    int o = threadIdx.x;

    float ak = kb[o], av = vb[o];
    #pragma unroll
    for (int hg = 0; hg < 2; hg++) {
        int g = b * 2 + hg;
        float offRow = offr[(size_t)(g * 2048 + r) * 64 + w];
        float offCol = offr[(size_t)(g * 2048 + 1024 + r) * 64 + w];
        float rows = fmaf(tanhf(offRow), 0.984375f, (float)ri2);
        float cols = fmaf(tanhf(offCol), 0.984375f, (float)ci2);
        float r0f = floorf(rows), c0f = floorf(cols);
        float fr = rows - r0f, fc = cols - c0f;
        int r0 = (int)r0f, c0 = (int)c0f;
        const float* pk = pkT + (size_t)g * HWPIX * 256 + o;
        const float* pv = pvT + (size_t)g * HWPIX * 256 + o;
        float w00 = (1.f - fr) * (1.f - fc), w01 = (1.f - fr) * fc;
        float w10 = fr * (1.f - fc),         w11 = fr * fc;
        if (r0 >= 0 && r0 < 64) {
            if (c0 >= 0 && c0 < 64) {
                size_t p = (size_t)(r0 * 64 + c0) * 256;
                ak = fmaf(pk[p], w00, ak); av = fmaf(pv[p], w00, av);
            }
            if (c0 + 1 >= 0 && c0 + 1 < 64) {
                size_t p = (size_t)(r0 * 64 + c0 + 1) * 256;
                ak = fmaf(pk[p], w01, ak); av = fmaf(pv[p], w01, av);
            }
        }
        if (r0 + 1 >= 0 && r0 + 1 < 64) {
            if (c0 >= 0 && c0 < 64) {
                size_t p = (size_t)((r0 + 1) * 64 + c0) * 256;
                ak = fmaf(pk[p], w10, ak); av = fmaf(pv[p], w10, av);
            }
            if (c0 + 1 >= 0 && c0 + 1 < 64) {
                size_t p = (size_t)((r0 + 1) * 64 + c0 + 1) * 256;
                ak = fmaf(pk[p], w11, ak); av = fmaf(pv[p], w11, av);
            }
        }
    }
    size_t oi = (size_t)blk * 256 + o;
    kkT[oi] = ak;
    vvT[oi] = av;
}

// ------------------------------ attention ----------------------------------
__global__ __launch_bounds__(256, 2) void attn_kernel(
    const float* __restrict__ qb, const float* __restrict__ kkT,
    const float* __restrict__ vvT, const float* __restrict__ pos,
    float* __restrict__ outT)
{
    __shared__ float wq_s[64][33];
    __shared__ float kk_s[64][36];
    __shared__ float vv_s[64][36];
    const int w = blockIdx.x, h = blockIdx.y, b = blockIdx.z;
    const int wh = w >> 3, wwx = w & 7;
    const int tid = threadIdx.x;

    for (int e = tid; e < 2048; e += 256) {
        int qq = e >> 5, c = e & 31;
        int yy = (wh << 3) + (qq >> 3), xx = (wwx << 3) + (qq & 7);
        wq_s[qq][c] = qb[(size_t)(b * 256 + h * 32 + c) * HWPIX + yy * 64 + xx] * 0.0625f;
    }
    __syncthreads();

    const int q = tid >> 2, lane = tid & 3;
    const int y = (wh << 3) + (q >> 3), x = (wwx << 3) + (q & 7);
    u64p wq2[16];
    #pragma unroll
    for (int c2 = 0; c2 < 16; c2++)
        wq2[c2] = pack2(wq_s[q][c2 * 2], wq_s[q][c2 * 2 + 1]);

    const float* posh = pos + h * 127 * 127 + (63 - y) * 127 + (63 - x);
    float m = -1e30f, s = 0.f;
    u64p acc2[16];
    #pragma unroll
    for (int c2 = 0; c2 < 16; c2++) acc2[c2] = 0ULL;

    const size_t kvbase = ((size_t)b * NPIX_S + (size_t)w * 1024) * 256 + h * 32;
    const int rr_l = tid >> 2;          // 0..63 (row within tile)
    const int c8   = (tid & 3) << 3;    // 0,8,16,24 (channel sub-block)

    for (int r0 = 0; r0 < 1024; r0 += 64) {
        __syncthreads();
        {
            const float* kp = kkT + kvbase + (size_t)(r0 + rr_l) * 256 + c8;
            const float* vp = vvT + kvbase + (size_t)(r0 + rr_l) * 256 + c8;
            float4 k0 = *(const float4*)kp;  float4 k1 = *(const float4*)(kp + 4);
            float4 v0 = *(const float4*)vp;  float4 v1 = *(const float4*)(vp + 4);
            *(float4*)&kk_s[rr_l][c8]     = k0;
            *(float4*)&kk_s[rr_l][c8 + 4] = k1;
            *(float4*)&vv_s[rr_l][c8]     = v0;
            *(float4*)&vv_s[rr_l][c8 + 4] = v1;
        }
        __syncthreads();

        #pragma unroll 4
        for (int t = 0; t < 16; t++) {
            int rr = (t << 2) + lane;
            int r  = r0 + rr;
            float bv = posh[((r >> 5) << 1) * 127 + ((r & 31) << 1)];
            const u64p* krow = (const u64p*)&kk_s[rr][0];
            u64p sc2 = 0ULL;
            #pragma unroll
            for (int c2 = 0; c2 < 16; c2++) sc2 = fma2(wq2[c2], krow[c2], sc2);
            float2 u = unpack2(sc2);
            float sc = u.x + u.y + bv;
            const u64p* vrow = (const u64p*)&vv_s[rr][0];
            if (sc > m) {
                float corr = fexp(m - sc);
                s = fmaf(s, corr, 1.0f);
                u64p cp2 = pack2(corr, corr);
                #pragma unroll
                for (int c2 = 0; c2 < 16; c2++)
                    acc2[c2] = fma2(acc2[c2], cp2, vrow[c2]);
                m = sc;
            } else {
                float p = fexp(sc - m);
                s += p;
                u64p p2 = pack2(p, p);
                #pragma unroll
                for (int c2 = 0; c2 < 16; c2++)
                    acc2[c2] = fma2(p2, vrow[c2], acc2[c2]);
            }
        }
    }

    // merge 4 lanes of each query
    float M = m;
    M = fmaxf(M, __shfl_xor_sync(0xffffffffu, M, 1));
    M = fmaxf(M, __shfl_xor_sync(0xffffffffu, M, 2));
    float corr = fexp(m - M);
    s *= corr;
    s += __shfl_xor_sync(0xffffffffu, s, 1);
    s += __shfl_xor_sync(0xffffffffu, s, 2);
    float accs[32];
    #pragma unroll
    for (int c2 = 0; c2 < 16; c2++) {
        float2 u = unpack2(acc2[c2]);
        accs[c2 * 2] = u.x; accs[c2 * 2 + 1] = u.y;
    }
    #pragma unroll
    for (int c = 0; c < 32; c++) {
        float a = accs[c] * corr;
        a += __shfl_xor_sync(0xffffffffu, a, 1);
        a += __shfl_xor_sync(0xffffffffu, a, 2);
        accs[c] = a;
    }
    if (lane == 0) {
        float inv = 1.0f / s;
        float* op = outT + ((size_t)b * HWPIX + y * 64 + x) * 256 + h * 32;
        #pragma unroll
        for (int c = 0; c < 32; c++) op[c] = accs[c] * inv;
    }
}

// ------------------------------ launch -------------------------------------
extern "C" void kernel_launch(void* const* d_in, const int* in_sizes, int n_in,
                              void* d_out, int out_size)
{
    const float* x      = (const float*)d_in[0];
    const float* ln1_g  = (const float*)d_in[1];
    const float* ln1_b  = (const float*)d_in[2];
    const float* q_w    = (const float*)d_in[3];
    const float* q_b    = (const float*)d_in[4];
    const float* k_w    = (const float*)d_in[5];
    const float* k_b    = (const float*)d_in[6];
    const float* v_w    = (const float*)d_in[7];
    const float* v_b    = (const float*)d_in[8];
    const float* off1_w = (const float*)d_in[9];
    const float* off2_w = (const float*)d_in[10];
    const float* off3_w = (const float*)d_in[11];
    const float* bn_g   = (const float*)d_in[12];
    const float* bn_b   = (const float*)d_in[13];
    const float* bn_m   = (const float*)d_in[14];
    const float* bn_v   = (const float*)d_in[15];
    const float* off4_w = (const float*)d_in[16];
    const float* pos    = (const float*)d_in[17];
    const float* proj_w = (const float*)d_in[18];
    const float* proj_b = (const float*)d_in[19];
    const float* ln2_g  = (const float*)d_in[20];
    const float* ln2_b  = (const float*)d_in[21];
    const float* mlp_w1 = (const float*)d_in[22];
    const float* mlp_b1 = (const float*)d_in[23];
    const float* mlp_w2 = (const float*)d_in[24];
    const float* mlp_b2 = (const float*)d_in[25];
    float* out = (float*)d_out;

    float *xaT, *q, *t1, *t2, *t3, *oT, *offr, *pkT, *pvT, *kkb, *vvb, *attnT, *x2, *xmT, *hidT;
    cudaGetSymbolAddress((void**)&xaT,   g_xaT);
    cudaGetSymbolAddress((void**)&q,     g_q);
    cudaGetSymbolAddress((void**)&t1,    g_t1);
    cudaGetSymbolAddress((void**)&t2,    g_t2);
    cudaGetSymbolAddress((void**)&t3,    g_t3);
    cudaGetSymbolAddress((void**)&oT,    g_oT);
    cudaGetSymbolAddress((void**)&offr,  g_offr);
    cudaGetSymbolAddress((void**)&pkT,   g_pk);
    cudaGetSymbolAddress((void**)&pvT,   g_pv);
    cudaGetSymbolAddress((void**)&kkb,   g_kk);
    cudaGetSymbolAddress((void**)&vvb,   g_vv);
    cudaGetSymbolAddress((void**)&attnT, g_attnT);
    cudaGetSymbolAddress((void**)&x2,    g_x2);
    cudaGetSymbolAddress((void**)&xmT,   g_xmT);
    cudaGetSymbolAddress((void**)&hidT,  g_hidT);

    // 1. LN1: x (B,C,HW) C-major -> xaT pixel-major
    ln_kernel<<<8192, 256>>>(x, ln1_g, ln1_b, xaT,
                             (size_t)CDIM * HWPIX, (size_t)HWPIX, (size_t)1);

    // 2. q = q_w @ xa + q_b  -> C-major (B,256,4096)
    gemm_tn<<<dim3(HWPIX / 64, CDIM / 128, NB), 256>>>(
        q_w, CDIM, xaT, CDIM, (size_t)HWPIX * CDIM,
        q_b, nullptr, q, CDIM, HWPIX, CDIM, 0);

    // 3. offset path: 3x depthwise stride-2 convs (q viewed as (4,128,64,64))
    dw_conv<<<(4 * 128 * 32 * 32 + 255) / 256, 256>>>(q,  off1_w, t1, 64, 32);
    dw_conv<<<(4 * 128 * 16 * 16 + 255) / 256, 256>>>(t1, off2_w, t2, 32, 16);
    dw_conv<<<(4 * 128 *  8 *  8 + 255) / 256, 256>>>(t2, off3_w, t3, 16, 8);

    // 4. BN + GELU, transpose to pixel-major
    bn_gelu_t<<<(4 * 128 * 64 + 255) / 256, 256>>>(t3, bn_g, bn_b, bn_m, bn_v, oT);

    // 5. off4: (2048x128) @ (64x128)^T per group -> offr C-major (4,2048,64)
    gemm_tn<<<dim3(1, 2048 / 128, 4), 256>>>(
        off4_w, 128, oT, 128, (size_t)64 * 128,
        nullptr, nullptr, offr, 2048, 64, 128, 0);

    // 6a/6b. partial conv maps: pk[b,g] = k_w[:,g-chans] @ xa[g-chans]
    gemm_tn<<<dim3(HWPIX / 64, 2, 4), 256>>>(
        k_w, CDIM, xaT, CDIM, 0,
        nullptr, nullptr, pkT, CDIM, HWPIX, GC, GF_GROUPED | GF_OUT_NMAJOR);
    gemm_tn<<<dim3(HWPIX / 64, 2, 4), 256>>>(
        v_w, CDIM, xaT, CDIM, 0,
        nullptr, nullptr, pvT, CDIM, HWPIX, GC, GF_GROUPED | GF_OUT_NMAJOR);

    // 7. fused deformable sampling of partial maps -> kk/vv pixel-major
    sample_kv<<<NB * NPIX_S, 256>>>(offr, pkT, pvT, k_b, v_b, kkb, vvb);

    // 8. windowed attention with rel-pos bias -> attnT pixel-major
    attn_kernel<<<dim3(NWIN, HEADS, NB), 256>>>(q, kkb, vvb, pos, attnT);

    // 9. proj + residual(x, C-major) -> x2 pixel-major
    gemm_tn<<<dim3(HWPIX / 64, CDIM / 128, NB), 256>>>(
        proj_w, CDIM, attnT, CDIM, (size_t)HWPIX * CDIM,
        proj_b, x, x2, CDIM, HWPIX, CDIM, GF_OUT_NMAJOR);

    // 10. LN2 on x2 (pixel-major) -> xmT pixel-major
    ln_kernel<<<8192, 256>>>(x2, ln2_g, ln2_b, xmT,
                             (size_t)HWPIX * CDIM, (size_t)1, (size_t)CDIM);

    // 11. mlp1 + gelu -> hidT pixel-major (B,4096,1024)
    gemm_tn<<<dim3(HWPIX / 64, MLPH / 128, NB), 256>>>(
        mlp_w1, CDIM, xmT, CDIM, (size_t)HWPIX * CDIM,
        mlp_b1, nullptr, hidT, MLPH, HWPIX, CDIM, GF_OUT_NMAJOR | GF_GELU);

    // 12. mlp2 + residual(x2, pixel-major) -> out C-major (B,256,64,64)
    gemm_tn<<<dim3(HWPIX / 64, CDIM / 128, NB), 256>>>(
        mlp_w2, MLPH, hidT, MLPH, (size_t)HWPIX * MLPH,
        mlp_b2, x2, out, CDIM, HWPIX, MLPH, GF_RES_NMAJOR);
}

// round 9
// speedup vs baseline: 2.8230x; 1.6403x over previous
#include <cuda_runtime.h>
#include <cuda_bf16.h>
#include <cstdint>
#include <cstddef>

// ---------------------------------------------------------------------------
// Problem constants
//   B=2, DIM=256, H=W=64, HEADS=8 (HC=32), HG=2 (GC=128), STRIDE=2,
//   WS=8 (NW=64 windows of WT=64 queries), RH=RW=32 (R=1024), MLP_HID=1024
// ---------------------------------------------------------------------------

#define NB      2
#define CDIM    256
#define HWPIX   4096            // 64*64
#define HEADS   8
#define HC      32
#define HG      2
#define GC      128
#define RPTS    1024            // R
#define NWIN    64              // NW
#define NPIX_S  65536           // NW * R
#define MLPH    1024

// ----------------------------- scratch ------------------------------------
__device__ float g_xaT [NB * HWPIX * CDIM];            // LN1 out, pixel-major
__device__ float g_q   [NB * CDIM * HWPIX];            // q conv out, C-major
__device__ float g_t1  [4 * 128 * 32 * 32];
__device__ float g_t2  [4 * 128 * 16 * 16];
__device__ float g_t3  [4 * 128 * 8 * 8];
__device__ float g_oT  [4 * 64 * 128];                 // bn+gelu out, pixel-major
__device__ float g_offr[4 * 2048 * 64];                // off4 out, C-major
__device__ float g_pk  [4 * HWPIX * CDIM];             // partial k maps, pixel-major
__device__ float g_pv  [4 * HWPIX * CDIM];             // partial v maps, pixel-major
__device__ float g_kk  [(size_t)NB * NPIX_S * CDIM];   // kk pixel-major [(b,w,r),c]
__device__ float g_vv  [(size_t)NB * NPIX_S * CDIM];   // vv pixel-major
__device__ float g_attnT[NB * HWPIX * CDIM];           // attention out, pixel-major
__device__ float g_x2  [NB * HWPIX * CDIM];            // x + proj, pixel-major
__device__ float g_xmT [NB * HWPIX * CDIM];            // LN2 out, pixel-major
__device__ float g_hidT[(size_t)NB * HWPIX * MLPH];    // mlp hidden, pixel-major

// ----------------------------- helpers ------------------------------------
__device__ __forceinline__ float geluf(float v) {
    return 0.5f * v * (1.0f + erff(v * 0.70710678118654752f));
}

// tf32 round-to-nearest conversion (kept in f32 container).
__device__ __forceinline__ float to_tf32(float x) {
    uint32_t u;
    asm("cvt.rna.tf32.f32 %0, %1;" : "=r"(u) : "f"(x));
    return __uint_as_float(u);
}

// m16n8k8 TF32 tensor-core MMA (fp32 accumulate).
__device__ __forceinline__ void mma_tf32(float* d, const uint32_t* a, const uint32_t* b) {
    asm volatile(
        "mma.sync.aligned.m16n8k8.row.col.f32.tf32.tf32.f32 "
        "{%0,%1,%2,%3}, {%4,%5,%6,%7}, {%8,%9}, {%0,%1,%2,%3};"
        : "+f"(d[0]), "+f"(d[1]), "+f"(d[2]), "+f"(d[3])
        : "r"(a[0]), "r"(a[1]), "r"(a[2]), "r"(a[3]), "r"(b[0]), "r"(b[1]));
}

// Fast exp on the FMA pipe. Degree-5 poly for 2^f, rel err ~8e-5.
__device__ __forceinline__ float fexp(float x) {
    float y = x * 1.4426950408889634f;
    y = fmaxf(y, -126.0f);
    float fi = floorf(y);
    float f = y - fi;
    float p = 0.0013333558f;
    p = fmaf(p, f, 0.0096181291f);
    p = fmaf(p, f, 0.0555041087f);
    p = fmaf(p, f, 0.2402264923f);
    p = fmaf(p, f, 0.6931471806f);
    p = fmaf(p, f, 1.0f);
    int e = (int)fi;
    return p * __int_as_float((e + 127) << 23);
}

// ----------------------------- LayerNorm -----------------------------------
__global__ __launch_bounds__(256) void ln_kernel(
    const float* __restrict__ in, const float* __restrict__ gam,
    const float* __restrict__ bet, float* __restrict__ outT,
    size_t bStride, size_t cStride, size_t pStride)
{
    int p  = blockIdx.x;            // 0..8191
    int b  = p >> 12;
    int hw = p & 4095;
    const float* ip = in + (size_t)b * bStride + (size_t)hw * pStride;
    int c = threadIdx.x;
    float v = ip[(size_t)c * cStride];
    float s1 = v, s2 = v * v;
    #pragma unroll
    for (int d = 16; d > 0; d >>= 1) {
        s1 += __shfl_xor_sync(0xffffffffu, s1, d);
        s2 += __shfl_xor_sync(0xffffffffu, s2, d);
    }
    __shared__ float sm1[8], sm2[8];
    __shared__ float mu_s, ri_s;
    int wid = c >> 5;
    if ((c & 31) == 0) { sm1[wid] = s1; sm2[wid] = s2; }
    __syncthreads();
    if (c == 0) {
        float t1 = 0.f, t2 = 0.f;
        #pragma unroll
        for (int i = 0; i < 8; i++) { t1 += sm1[i]; t2 += sm2[i]; }
        float mu  = t1 * (1.0f / 256.0f);
        float var = t2 * (1.0f / 256.0f) - mu * mu;
        mu_s = mu;
        ri_s = rsqrtf(var + 1e-5f);
    }
    __syncthreads();
    outT[(size_t)p * 256 + c] = (v - mu_s) * ri_s * gam[c] + bet[c];
}

// ----------------------------- GEMM (TN, TF32 tensor core) ------------------
// C[z] = A(MxK, lda) * B[z](NxK, ldb)^T (+bias)(gelu?)(+res?).
// BM=128, BN=64, BK=32; 8 warps (4 m x 2 n), each 32x32 via 2x4 m16n8k8 frags.
#define GF_OUT_NMAJOR 1
#define GF_RES_NMAJOR 2
#define GF_GELU       4
#define GF_GROUPED    8

__global__ __launch_bounds__(256) void gemm_tn(
    const float* __restrict__ A, int lda,
    const float* __restrict__ Bm, int ldb, size_t bZ,
    const float* __restrict__ bias, const float* __restrict__ res,
    float* __restrict__ C, int M, int N, int K, int flags)
{
    __shared__ float As[128][36];
    __shared__ float Bs[64][36];
    const int b  = blockIdx.z;
    const int m0 = blockIdx.y * 128;
    const int n0 = blockIdx.x * 64;
    const float* Ab = A;
    const float* Bb;
    if (flags & GF_GROUPED) {
        Ab = A + (b & 1) * 128;
        Bb = Bm + (size_t)(b >> 1) * ((size_t)HWPIX * 256) + (b & 1) * 128;
    } else {
        Bb = Bm + (size_t)b * bZ;
    }
    const int tid  = threadIdx.x;
    const int warp = tid >> 5, lane = tid & 31;
    const int g = lane >> 2, tg = lane & 3;
    const int wm = warp & 3;        // 0..3 -> 32-row m block
    const int wn = warp >> 2;       // 0..1 -> 32-col n block

    float acc[2][4][4];
    #pragma unroll
    for (int mi = 0; mi < 2; mi++)
        #pragma unroll
        for (int nj = 0; nj < 4; nj++)
            #pragma unroll
            for (int e = 0; e < 4; e++) acc[mi][nj][e] = 0.f;

    for (int k0 = 0; k0 < K; k0 += 32) {
        #pragma unroll
        for (int i = 0; i < 4; i++) {
            int e = tid + i * 256;
            int row = e >> 3, c4 = (e & 7) << 2;
            float4 a = *(const float4*)(Ab + (size_t)(m0 + row) * lda + k0 + c4);
            As[row][c4    ] = to_tf32(a.x);
            As[row][c4 + 1] = to_tf32(a.y);
            As[row][c4 + 2] = to_tf32(a.z);
            As[row][c4 + 3] = to_tf32(a.w);
        }
        #pragma unroll
        for (int i = 0; i < 2; i++) {
            int e = tid + i * 256;
            int row = e >> 3, c4 = (e & 7) << 2;
            float4 v = *(const float4*)(Bb + (size_t)(n0 + row) * ldb + k0 + c4);
            Bs[row][c4    ] = to_tf32(v.x);
            Bs[row][c4 + 1] = to_tf32(v.y);
            Bs[row][c4 + 2] = to_tf32(v.z);
            Bs[row][c4 + 3] = to_tf32(v.w);
        }
        __syncthreads();

        #pragma unroll
        for (int kk = 0; kk < 4; kk++) {
            int kb = kk * 8;
            uint32_t af[2][4], bf[4][2];
            #pragma unroll
            for (int mi = 0; mi < 2; mi++) {
                int mr = wm * 32 + mi * 16;
                af[mi][0] = __float_as_uint(As[mr + g    ][kb + tg    ]);
                af[mi][1] = __float_as_uint(As[mr + g + 8][kb + tg    ]);
                af[mi][2] = __float_as_uint(As[mr + g    ][kb + tg + 4]);
                af[mi][3] = __float_as_uint(As[mr + g + 8][kb + tg + 4]);
            }
            #pragma unroll
            for (int nj = 0; nj < 4; nj++) {
                int nr = wn * 32 + nj * 8;
                bf[nj][0] = __float_as_uint(Bs[nr + g][kb + tg    ]);
                bf[nj][1] = __float_as_uint(Bs[nr + g][kb + tg + 4]);
            }
            #pragma unroll
            for (int mi = 0; mi < 2; mi++)
                #pragma unroll
                for (int nj = 0; nj < 4; nj++)
                    mma_tf32(acc[mi][nj], af[mi], bf[nj]);
        }
        __syncthreads();
    }

    #pragma unroll
    for (int mi = 0; mi < 2; mi++) {
        #pragma unroll
        for (int nj = 0; nj < 4; nj++) {
            int nc = n0 + wn * 32 + nj * 8 + tg * 2;
            #pragma unroll
            for (int e = 0; e < 4; e++) {
                int m = m0 + wm * 32 + mi * 16 + g + (e >> 1) * 8;
                int n = nc + (e & 1);
                float v = acc[mi][nj][e];
                if (bias) v += bias[m];
                if (flags & GF_GELU) v = geluf(v);
                if (res) {
                    size_t ri = (flags & GF_RES_NMAJOR)
                        ? ((size_t)b * N + n) * (size_t)M + m
                        : ((size_t)b * M + m) * (size_t)N + n;
                    v += res[ri];
                }
                size_t oi = (flags & GF_OUT_NMAJOR)
                    ? ((size_t)b * N + n) * (size_t)M + m
                    : ((size_t)b * M + m) * (size_t)N + n;
                C[oi] = v;
            }
        }
    }
}

// ------------------------ depthwise 3x3 stride-2 ---------------------------
__global__ void dw_conv(const float* __restrict__ in, const float* __restrict__ w,
                        float* __restrict__ out, int Hi, int Ho)
{
    int idx = blockIdx.x * blockDim.x + threadIdx.x;
    int total = 4 * 128 * Ho * Ho;
    if (idx >= total) return;
    int ox = idx % Ho;
    int oy = (idx / Ho) % Ho;
    int c  = (idx / (Ho * Ho)) % 128;
    int g  = idx / (Ho * Ho * 128);
    const float* ip = in + (size_t)(g * 128 + c) * Hi * Hi;
    const float* wp = w + c * 9;
    float s = 0.f;
    #pragma unroll
    for (int ky = 0; ky < 3; ky++) {
        int iy = oy * 2 - 1 + ky;
        if (iy < 0 || iy >= Hi) continue;
        #pragma unroll
        for (int kx = 0; kx < 3; kx++) {
            int ix = ox * 2 - 1 + kx;
            if (ix < 0 || ix >= Hi) continue;
            s = fmaf(ip[iy * Hi + ix], wp[ky * 3 + kx], s);
        }
    }
    out[idx] = s;
}

// ------------------------- BN + GELU + transpose ---------------------------
__global__ void bn_gelu_t(const float* __restrict__ t3, const float* __restrict__ g,
                          const float* __restrict__ b, const float* __restrict__ m,
                          const float* __restrict__ v, float* __restrict__ oT)
{
    int idx = blockIdx.x * blockDim.x + threadIdx.x;
    if (idx >= 4 * 128 * 64) return;
    int wsp = idx % 64;
    int c   = (idx / 64) % 128;
    int gg  = idx / (64 * 128);
    float x = t3[idx];
    x = (x - m[c]) * rsqrtf(v[c] + 1e-5f) * g[c] + b[c];
    x = geluf(x);
    oT[(size_t)(gg * 64 + wsp) * 128 + c] = x;
}

// ------------------------- fused k/v deformable sampling -------------------
__global__ __launch_bounds__(256) void sample_kv(
    const float* __restrict__ offr, const float* __restrict__ pkT,
    const float* __restrict__ pvT, const float* __restrict__ kb,
    const float* __restrict__ vb, float* __restrict__ kkT,
    float* __restrict__ vvT)
{
    int blk = blockIdx.x;           // b*65536 + w*1024 + r
    int b = blk >> 16;
    int w = (blk >> 10) & 63;
    int r = blk & 1023;
    int ri2 = (r >> 5) << 1;
    int ci2 = (r & 31) << 1;
    int o = threadIdx.x;

    float ak = kb[o], av = vb[o];
    #pragma unroll
    for (int hg = 0; hg < 2; hg++) {
        int g = b * 2 + hg;
        float offRow = offr[(size_t)(g * 2048 + r) * 64 + w];
        float offCol = offr[(size_t)(g * 2048 + 1024 + r) * 64 + w];
        float rows = fmaf(tanhf(offRow), 0.984375f, (float)ri2);
        float cols = fmaf(tanhf(offCol), 0.984375f, (float)ci2);
        float r0f = floorf(rows), c0f = floorf(cols);
        float fr = rows - r0f, fc = cols - c0f;
        int r0 = (int)r0f, c0 = (int)c0f;
        const float* pk = pkT + (size_t)g * HWPIX * 256 + o;
        const float* pv = pvT + (size_t)g * HWPIX * 256 + o;
        float w00 = (1.f - fr) * (1.f - fc), w01 = (1.f - fr) * fc;
        float w10 = fr * (1.f - fc),         w11 = fr * fc;
        if (r0 >= 0 && r0 < 64) {
            if (c0 >= 0 && c0 < 64) {
                size_t p = (size_t)(r0 * 64 + c0) * 256;
                ak = fmaf(pk[p], w00, ak); av = fmaf(pv[p], w00, av);
            }
            if (c0 + 1 >= 0 && c0 + 1 < 64) {
                size_t p = (size_t)(r0 * 64 + c0 + 1) * 256;
                ak = fmaf(pk[p], w01, ak); av = fmaf(pv[p], w01, av);
            }
        }
        if (r0 + 1 >= 0 && r0 + 1 < 64) {
            if (c0 >= 0 && c0 < 64) {
                size_t p = (size_t)((r0 + 1) * 64 + c0) * 256;
                ak = fmaf(pk[p], w10, ak); av = fmaf(pv[p], w10, av);
            }
            if (c0 + 1 >= 0 && c0 + 1 < 64) {
                size_t p = (size_t)((r0 + 1) * 64 + c0 + 1) * 256;
                ak = fmaf(pk[p], w11, ak); av = fmaf(pv[p], w11, av);
            }
        }
    }
    size_t oi = (size_t)blk * 256 + o;
    kkT[oi] = ak;
    vvT[oi] = av;
}

// ------------------------------ attention (TF32 tensor core) ----------------
// One block per (b, head, window). 128 threads = 4 warps; warp wq owns q rows
// [16wq,16wq+16). Flash-style: per 64-r tile, S = Q·K^T via m16n8k8, bias
// gathered per element, online softmax (row stats redundant across tg lanes),
// P (tf32) through smem, O += P·V via m16n8k8.
__global__ __launch_bounds__(128) void attn_kernel(
    const float* __restrict__ qb, const float* __restrict__ kkT,
    const float* __restrict__ vvT, const float* __restrict__ pos,
    float* __restrict__ outT)
{
    __shared__ float Qs[64][36];    // q rows x 32c (tf32, pre-scaled)
    __shared__ float Ks[64][36];    // r rows x 32c (tf32)
    __shared__ float VsT[32][69];   // 32c x 64r (tf32) — pad 69: staging conflict-free
    __shared__ float Ps[64][68];    // q rows x 64r probs (tf32)

    const int w = blockIdx.x, h = blockIdx.y, b = blockIdx.z;
    const int wh = w >> 3, wwx = w & 7;
    const int tid = threadIdx.x;
    const int warp = tid >> 5, lane = tid & 31;
    const int g = lane >> 2, tg = lane & 3;

    // stage Q (scaled by C^-0.5 = 1/16, tf32)
    for (int e = tid; e < 2048; e += 128) {
        int qq = e >> 5, c = e & 31;
        int yy = (wh << 3) + (qq >> 3), xx = (wwx << 3) + (qq & 7);
        Qs[qq][c] = to_tf32(qb[(size_t)(b * 256 + h * 32 + c) * HWPIX + yy * 64 + xx] * 0.0625f);
    }

    // this thread's two q rows (within warp slice) and their bias bases
    const int qA = warp * 16 + g, qB = qA + 8;
    const int yA = (wh << 3) + (qA >> 3), xA = (wwx << 3) + (qA & 7);
    const int yB = (wh << 3) + (qB >> 3), xB = (wwx << 3) + (qB & 7);
    const float* poshA = pos + h * 127 * 127 + (63 - yA) * 127 + (63 - xA);
    const float* poshB = pos + h * 127 * 127 + (63 - yB) * 127 + (63 - xB);

    float mA = -1e30f, sA = 0.f, mB = -1e30f, sB = 0.f;
    float O[4][4];
    #pragma unroll
    for (int nj = 0; nj < 4; nj++)
        #pragma unroll
        for (int e = 0; e < 4; e++) O[nj][e] = 0.f;

    const size_t kvbase = ((size_t)b * NPIX_S + (size_t)w * 1024) * 256 + h * 32;
    const int srow = tid >> 1, shalf = tid & 1;   // staging map: row 0..63, half 0..1

    for (int r0 = 0; r0 < 1024; r0 += 64) {
        __syncthreads();
        // stage K [r][c] and V transposed [c][r]
        {
            const float* kp = kkT + kvbase + (size_t)(r0 + srow) * 256 + shalf * 16;
            const float* vp = vvT + kvbase + (size_t)(r0 + srow) * 256 + shalf * 16;
            #pragma unroll
            for (int i = 0; i < 4; i++) {
                float4 kv = *(const float4*)(kp + i * 4);
                Ks[srow][shalf * 16 + i * 4    ] = to_tf32(kv.x);
                Ks[srow][shalf * 16 + i * 4 + 1] = to_tf32(kv.y);
                Ks[srow][shalf * 16 + i * 4 + 2] = to_tf32(kv.z);
                Ks[srow][shalf * 16 + i * 4 + 3] = to_tf32(kv.w);
            }
            #pragma unroll
            for (int i = 0; i < 4; i++) {
                float4 vv4 = *(const float4*)(vp + i * 4);
                VsT[shalf * 16 + i * 4    ][srow] = to_tf32(vv4.x);
                VsT[shalf * 16 + i * 4 + 1][srow] = to_tf32(vv4.y);
                VsT[shalf * 16 + i * 4 + 2][srow] = to_tf32(vv4.z);
                VsT[shalf * 16 + i * 4 + 3][srow] = to_tf32(vv4.w);
            }
        }
        __syncthreads();

        // S[16q x 64r] per warp = Q Kt
        float S[8][4];
        #pragma unroll
        for (int nj = 0; nj < 8; nj++)
            #pragma unroll
            for (int e = 0; e < 4; e++) S[nj][e] = 0.f;
        #pragma unroll
        for (int kk = 0; kk < 4; kk++) {
            int kb = kk * 8;
            uint32_t af[4];
            af[0] = __float_as_uint(Qs[warp * 16 + g    ][kb + tg    ]);
            af[1] = __float_as_uint(Qs[warp * 16 + g + 8][kb + tg    ]);
            af[2] = __float_as_uint(Qs[warp * 16 + g    ][kb + tg + 4]);
            af[3] = __float_as_uint(Qs[warp * 16 + g + 8][kb + tg + 4]);
            #pragma unroll
            for (int nj = 0; nj < 8; nj++) {
                uint32_t bf[2];
                bf[0] = __float_as_uint(Ks[nj * 8 + g][kb + tg    ]);
                bf[1] = __float_as_uint(Ks[nj * 8 + g][kb + tg + 4]);
                mma_tf32(S[nj], af, bf);
            }
        }

        // add relative-position bias
        #pragma unroll
        for (int nj = 0; nj < 8; nj++) {
            int r0c = r0 + nj * 8 + 2 * tg;
            int r1c = r0c + 1;
            int o0 = ((r0c >> 5) << 1) * 127 + ((r0c & 31) << 1);
            int o1 = ((r1c >> 5) << 1) * 127 + ((r1c & 31) << 1);
            S[nj][0] += poshA[o0];
            S[nj][1] += poshA[o1];
            S[nj][2] += poshB[o0];
            S[nj][3] += poshB[o1];
        }

        // online softmax (rows g, g+8; stats reduced over the 4 tg lanes)
        float mxA = -1e30f, mxB = -1e30f;
        #pragma unroll
        for (int nj = 0; nj < 8; nj++) {
            mxA = fmaxf(mxA, fmaxf(S[nj][0], S[nj][1]));
            mxB = fmaxf(mxB, fmaxf(S[nj][2], S[nj][3]));
        }
        mxA = fmaxf(mxA, __shfl_xor_sync(0xffffffffu, mxA, 1));
        mxA = fmaxf(mxA, __shfl_xor_sync(0xffffffffu, mxA, 2));
        mxB = fmaxf(mxB, __shfl_xor_sync(0xffffffffu, mxB, 1));
        mxB = fmaxf(mxB, __shfl_xor_sync(0xffffffffu, mxB, 2));
        float mnA = fmaxf(mA, mxA), mnB = fmaxf(mB, mxB);
        float corrA = fexp(mA - mnA), corrB = fexp(mB - mnB);
        mA = mnA; mB = mnB;

        float suA = 0.f, suB = 0.f;
        #pragma unroll
        for (int nj = 0; nj < 8; nj++) {
            float p0 = fexp(S[nj][0] - mnA);
            float p1 = fexp(S[nj][1] - mnA);
            float p2 = fexp(S[nj][2] - mnB);
            float p3 = fexp(S[nj][3] - mnB);
            suA += p0 + p1;
            suB += p2 + p3;
            int c0 = nj * 8 + 2 * tg;
            Ps[warp * 16 + g    ][c0    ] = to_tf32(p0);
            Ps[warp * 16 + g    ][c0 + 1] = to_tf32(p1);
            Ps[warp * 16 + g + 8][c0    ] = to_tf32(p2);
            Ps[warp * 16 + g + 8][c0 + 1] = to_tf32(p3);
        }
        suA += __shfl_xor_sync(0xffffffffu, suA, 1);
        suA += __shfl_xor_sync(0xffffffffu, suA, 2);
        suB += __shfl_xor_sync(0xffffffffu, suB, 1);
        suB += __shfl_xor_sync(0xffffffffu, suB, 2);
        sA = sA * corrA + suA;
        sB = sB * corrB + suB;

        // rescale O (c0,c1 = row g; c2,c3 = row g+8)
        #pragma unroll
        for (int nj = 0; nj < 4; nj++) {
            O[nj][0] *= corrA; O[nj][1] *= corrA;
            O[nj][2] *= corrB; O[nj][3] *= corrB;
        }
        __syncwarp();
        __syncthreads();   // Ps visible to all A-frag reads (warp-local, but keep block-wide)

        // O += P Vt : A = Ps [16q x 64k], B = VsT [32n x 64k]
        #pragma unroll
        for (int kk = 0; kk < 8; kk++) {
            int kb = kk * 8;
            uint32_t af[4];
            af[0] = __float_as_uint(Ps[warp * 16 + g    ][kb + tg    ]);
            af[1] = __float_as_uint(Ps[warp * 16 + g + 8][kb + tg    ]);
            af[2] = __float_as_uint(Ps[warp * 16 + g    ][kb + tg + 4]);
            af[3] = __float_as_uint(Ps[warp * 16 + g + 8][kb + tg + 4]);
            #pragma unroll
            for (int nj = 0; nj < 4; nj++) {
                uint32_t bf[2];
                bf[0] = __float_as_uint(VsT[nj * 8 + g][kb + tg    ]);
                bf[1] = __float_as_uint(VsT[nj * 8 + g][kb + tg + 4]);
                mma_tf32(O[nj], af, bf);
            }
        }
    }

    // epilogue: normalize and write (pixel-major, head slice)
    float invA = 1.0f / sA, invB = 1.0f / sB;
    float* opA = outT + ((size_t)b * HWPIX + yA * 64 + xA) * 256 + h * 32;
    float* opB = outT + ((size_t)b * HWPIX + yB * 64 + xB) * 256 + h * 32;
    #pragma unroll
    for (int nj = 0; nj < 4; nj++) {
        int c = nj * 8 + 2 * tg;
        opA[c]     = O[nj][0] * invA;
        opA[c + 1] = O[nj][1] * invA;
        opB[c]     = O[nj][2] * invB;
        opB[c + 1] = O[nj][3] * invB;
    }
}

// ------------------------------ launch -------------------------------------
extern "C" void kernel_launch(void* const* d_in, const int* in_sizes, int n_in,
                              void* d_out, int out_size)
{
    const float* x      = (const float*)d_in[0];
    const float* ln1_g  = (const float*)d_in[1];
    const float* ln1_b  = (const float*)d_in[2];
    const float* q_w    = (const float*)d_in[3];
    const float* q_b    = (const float*)d_in[4];
    const float* k_w    = (const float*)d_in[5];
    const float* k_b    = (const float*)d_in[6];
    const float* v_w    = (const float*)d_in[7];
    const float* v_b    = (const float*)d_in[8];
    const float* off1_w = (const float*)d_in[9];
    const float* off2_w = (const float*)d_in[10];
    const float* off3_w = (const float*)d_in[11];
    const float* bn_g   = (const float*)d_in[12];
    const float* bn_b   = (const float*)d_in[13];
    const float* bn_m   = (const float*)d_in[14];
    const float* bn_v   = (const float*)d_in[15];
    const float* off4_w = (const float*)d_in[16];
    const float* pos    = (const float*)d_in[17];
    const float* proj_w = (const float*)d_in[18];
    const float* proj_b = (const float*)d_in[19];
    const float* ln2_g  = (const float*)d_in[20];
    const float* ln2_b  = (const float*)d_in[21];
    const float* mlp_w1 = (const float*)d_in[22];
    const float* mlp_b1 = (const float*)d_in[23];
    const float* mlp_w2 = (const float*)d_in[24];
    const float* mlp_b2 = (const float*)d_in[25];
    float* out = (float*)d_out;

    float *xaT, *q, *t1, *t2, *t3, *oT, *offr, *pkT, *pvT, *kkb, *vvb, *attnT, *x2, *xmT, *hidT;
    cudaGetSymbolAddress((void**)&xaT,   g_xaT);
    cudaGetSymbolAddress((void**)&q,     g_q);
    cudaGetSymbolAddress((void**)&t1,    g_t1);
    cudaGetSymbolAddress((void**)&t2,    g_t2);
    cudaGetSymbolAddress((void**)&t3,    g_t3);
    cudaGetSymbolAddress((void**)&oT,    g_oT);
    cudaGetSymbolAddress((void**)&offr,  g_offr);
    cudaGetSymbolAddress((void**)&pkT,   g_pk);
    cudaGetSymbolAddress((void**)&pvT,   g_pv);
    cudaGetSymbolAddress((void**)&kkb,   g_kk);
    cudaGetSymbolAddress((void**)&vvb,   g_vv);
    cudaGetSymbolAddress((void**)&attnT, g_attnT);
    cudaGetSymbolAddress((void**)&x2,    g_x2);
    cudaGetSymbolAddress((void**)&xmT,   g_xmT);
    cudaGetSymbolAddress((void**)&hidT,  g_hidT);

    // 1. LN1: x (B,C,HW) C-major -> xaT pixel-major
    ln_kernel<<<8192, 256>>>(x, ln1_g, ln1_b, xaT,
                             (size_t)CDIM * HWPIX, (size_t)HWPIX, (size_t)1);

    // 2. q = q_w @ xa + q_b  -> C-major (B,256,4096)
    gemm_tn<<<dim3(HWPIX / 64, CDIM / 128, NB), 256>>>(
        q_w, CDIM, xaT, CDIM, (size_t)HWPIX * CDIM,
        q_b, nullptr, q, CDIM, HWPIX, CDIM, 0);

    // 3. offset path: 3x depthwise stride-2 convs (q viewed as (4,128,64,64))
    dw_conv<<<(4 * 128 * 32 * 32 + 255) / 256, 256>>>(q,  off1_w, t1, 64, 32);
    dw_conv<<<(4 * 128 * 16 * 16 + 255) / 256, 256>>>(t1, off2_w, t2, 32, 16);
    dw_conv<<<(4 * 128 *  8 *  8 + 255) / 256, 256>>>(t2, off3_w, t3, 16, 8);

    // 4. BN + GELU, transpose to pixel-major
    bn_gelu_t<<<(4 * 128 * 64 + 255) / 256, 256>>>(t3, bn_g, bn_b, bn_m, bn_v, oT);

    // 5. off4: (2048x128) @ (64x128)^T per group -> offr C-major (4,2048,64)
    gemm_tn<<<dim3(1, 2048 / 128, 4), 256>>>(
        off4_w, 128, oT, 128, (size_t)64 * 128,
        nullptr, nullptr, offr, 2048, 64, 128, 0);

    // 6a/6b. partial conv maps: pk[b,g] = k_w[:,g-chans] @ xa[g-chans]
    gemm_tn<<<dim3(HWPIX / 64, 2, 4), 256>>>(
        k_w, CDIM, xaT, CDIM, 0,
        nullptr, nullptr, pkT, CDIM, HWPIX, GC, GF_GROUPED | GF_OUT_NMAJOR);
    gemm_tn<<<dim3(HWPIX / 64, 2, 4), 256>>>(
        v_w, CDIM, xaT, CDIM, 0,
        nullptr, nullptr, pvT, CDIM, HWPIX, GC, GF_GROUPED | GF_OUT_NMAJOR);

    // 7. fused deformable sampling of partial maps -> kk/vv pixel-major
    sample_kv<<<NB * NPIX_S, 256>>>(offr, pkT, pvT, k_b, v_b, kkb, vvb);

    // 8. windowed attention with rel-pos bias -> attnT pixel-major
    attn_kernel<<<dim3(NWIN, HEADS, NB), 128>>>(q, kkb, vvb, pos, attnT);

    // 9. proj + residual(x, C-major) -> x2 pixel-major
    gemm_tn<<<dim3(HWPIX / 64, CDIM / 128, NB), 256>>>(
        proj_w, CDIM, attnT, CDIM, (size_t)HWPIX * CDIM,
        proj_b, x, x2, CDIM, HWPIX, CDIM, GF_OUT_NMAJOR);

    // 10. LN2 on x2 (pixel-major) -> xmT pixel-major
    ln_kernel<<<8192, 256>>>(x2, ln2_g, ln2_b, xmT,
                             (size_t)HWPIX * CDIM, (size_t)1, (size_t)CDIM);

    // 11. mlp1 + gelu -> hidT pixel-major (B,4096,1024)
    gemm_tn<<<dim3(HWPIX / 64, MLPH / 128, NB), 256>>>(
        mlp_w1, CDIM, xmT, CDIM, (size_t)HWPIX * CDIM,
        mlp_b1, nullptr, hidT, MLPH, HWPIX, CDIM, GF_OUT_NMAJOR | GF_GELU);

    // 12. mlp2 + residual(x2, pixel-major) -> out C-major (B,256,64,64)
    gemm_tn<<<dim3(HWPIX / 64, CDIM / 128, NB), 256>>>(
        mlp_w2, MLPH, hidT, MLPH, (size_t)HWPIX * MLPH,
        mlp_b2, x2, out, CDIM, HWPIX, MLPH, GF_RES_NMAJOR);
}